// round 1
// baseline (speedup 1.0000x reference)
#include <cuda_runtime.h>
#include <cuda_bf16.h>
#include <math.h>
#include <stdint.h>

// ---------------------------------------------------------------------------
// Problem: DCGCN. Shapes: U=I=50000 (N=100000), R=5, D=64, E=1e6 per rating,
// B=8192. Output: f32[B].
// ---------------------------------------------------------------------------

#define D 64
#define MAXN 100352
#define MLP_ROWS 128           // rows per block in MLP GEMM
#define MLP_THREADS 256

__device__ float g_buf0[(size_t)MAXN * D];
__device__ float g_buf1[(size_t)MAXN * D];
__device__ float g_sum [(size_t)MAXN * D];

// ---------------------------------------------------------------------------
// MLP kernel: h = leaky_relu(base @ W1a + c1) @ W2 + b2
//   c1 = b1[r] + rating_emb[r] @ W1[r][64:128]   (computed per block, cheap)
// Writes: prevbuf = h ; sum (+)= h ; aggbuf = 0
// Register-blocked GEMM: 256 threads, each computes 8 rows x 4 cols.
// Dynamic smem layout: xs[64][132] (x transposed), W1s[64*64], W2s[64*64],
//                      c1s[64], b2s[64]
// ---------------------------------------------------------------------------
__global__ void __launch_bounds__(MLP_THREADS) mlp_kernel(
    const float* __restrict__ user_emb, const float* __restrict__ item_emb,
    int U, int N,
    const float* __restrict__ W1, const float* __restrict__ b1,
    const float* __restrict__ W2, const float* __restrict__ b2,
    const float* __restrict__ rating_emb,
    int r, int first,
    float* __restrict__ prevbuf, float* __restrict__ aggbuf,
    float* __restrict__ sumbuf)
{
    extern __shared__ float smem[];
    float* xs  = smem;                   // 64*132
    float* W1s = xs + 64 * 132;          // 4096
    float* W2s = W1s + 64 * 64;          // 4096
    float* c1s = W2s + 64 * 64;          // 64
    float* b2s = c1s + 64;               // 64

    const float* W1r = W1 + (size_t)r * 128 * 64;
    const float* W2r = W2 + (size_t)r * 64 * 64;
    const int tid = threadIdx.x;
    const int row0 = blockIdx.x * MLP_ROWS;

    // Load W1a (rows 0..63) and W2 into smem (float4)
    for (int i = tid; i < 1024; i += MLP_THREADS) {
        ((float4*)W1s)[i] = ((const float4*)W1r)[i];
        ((float4*)W2s)[i] = ((const float4*)W2r)[i];
    }
    // c1 = b1 + rating_emb[r] @ W1[64:128]
    if (tid < 64) {
        float c = b1[r * 64 + tid];
        #pragma unroll 8
        for (int k = 0; k < 64; k++)
            c += rating_emb[r * 64 + k] * W1r[(64 + k) * 64 + tid];
        c1s[tid] = c;
        b2s[tid] = b2[r * 64 + tid];
    }
    // Load x transposed: xs[k*132 + row_in_block]
    for (int i = tid; i < MLP_ROWS * 16; i += MLP_THREADS) {
        int rr = i >> 4;
        int c4 = i & 15;
        int row = row0 + rr;
        float4 v = make_float4(0.f, 0.f, 0.f, 0.f);
        if (row < N) {
            const float* src = (row < U) ? (user_emb + (size_t)row * 64)
                                         : (item_emb + (size_t)(row - U) * 64);
            v = ((const float4*)src)[c4];
        }
        xs[(4 * c4 + 0) * 132 + rr] = v.x;
        xs[(4 * c4 + 1) * 132 + rr] = v.y;
        xs[(4 * c4 + 2) * 132 + rr] = v.z;
        xs[(4 * c4 + 3) * 132 + rr] = v.w;
    }
    __syncthreads();

    const int rg = tid >> 4;   // row group 0..15 (8 rows each)
    const int cg = tid & 15;   // col group 0..15 (4 cols each)

    // ---- layer 1 ----
    float acc[8][4];
    #pragma unroll
    for (int a = 0; a < 8; a++)
        #pragma unroll
        for (int bb = 0; bb < 4; bb++) acc[a][bb] = 0.f;

    #pragma unroll 8
    for (int k = 0; k < 64; k++) {
        float4 x0 = *(const float4*)(xs + k * 132 + rg * 8);
        float4 x1 = *(const float4*)(xs + k * 132 + rg * 8 + 4);
        float4 w  = *(const float4*)(W1s + k * 64 + cg * 4);
        float xv[8] = {x0.x, x0.y, x0.z, x0.w, x1.x, x1.y, x1.z, x1.w};
        #pragma unroll
        for (int a = 0; a < 8; a++) {
            acc[a][0] += xv[a] * w.x;
            acc[a][1] += xv[a] * w.y;
            acc[a][2] += xv[a] * w.z;
            acc[a][3] += xv[a] * w.w;
        }
    }
    __syncthreads();   // done reading xs; safe to overwrite

    // leaky_relu(acc + c1) -> xs (transposed)
    #pragma unroll
    for (int bb = 0; bb < 4; bb++) {
        float c = c1s[cg * 4 + bb];
        #pragma unroll
        for (int a = 0; a < 8; a++) {
            float v = acc[a][bb] + c;
            v = (v > 0.f) ? v : 0.01f * v;
            xs[(cg * 4 + bb) * 132 + rg * 8 + a] = v;
        }
    }
    __syncthreads();

    // ---- layer 2 ----
    #pragma unroll
    for (int a = 0; a < 8; a++)
        #pragma unroll
        for (int bb = 0; bb < 4; bb++) acc[a][bb] = 0.f;

    #pragma unroll 8
    for (int k = 0; k < 64; k++) {
        float4 x0 = *(const float4*)(xs + k * 132 + rg * 8);
        float4 x1 = *(const float4*)(xs + k * 132 + rg * 8 + 4);
        float4 w  = *(const float4*)(W2s + k * 64 + cg * 4);
        float xv[8] = {x0.x, x0.y, x0.z, x0.w, x1.x, x1.y, x1.z, x1.w};
        #pragma unroll
        for (int a = 0; a < 8; a++) {
            acc[a][0] += xv[a] * w.x;
            acc[a][1] += xv[a] * w.y;
            acc[a][2] += xv[a] * w.z;
            acc[a][3] += xv[a] * w.w;
        }
    }

    float4 bv = *(const float4*)(b2s + cg * 4);
    #pragma unroll
    for (int a = 0; a < 8; a++) {
        int row = row0 + rg * 8 + a;
        if (row < N) {
            float4 o = make_float4(acc[a][0] + bv.x, acc[a][1] + bv.y,
                                   acc[a][2] + bv.z, acc[a][3] + bv.w);
            size_t off = (size_t)row * 64 + cg * 4;
            *(float4*)(prevbuf + off) = o;
            if (first) {
                *(float4*)(sumbuf + off) = o;
            } else {
                float4 s = *(float4*)(sumbuf + off);
                s.x += o.x; s.y += o.y; s.z += o.z; s.w += o.w;
                *(float4*)(sumbuf + off) = s;
            }
            *(float4*)(aggbuf + off) = make_float4(0.f, 0.f, 0.f, 0.f);
        }
    }
}

// ---------------------------------------------------------------------------
// SpMM: agg[row] += val * prev[col]   (16 threads per edge, float4 + red.v4)
// ---------------------------------------------------------------------------
__device__ __forceinline__ void red_add_v4(float* addr, float4 v) {
    asm volatile("red.global.add.v4.f32 [%0], {%1,%2,%3,%4};"
                 :: "l"(addr), "f"(v.x), "f"(v.y), "f"(v.z), "f"(v.w)
                 : "memory");
}

__global__ void spmm_kernel(const int* __restrict__ rows,
                            const int* __restrict__ cols,
                            const float* __restrict__ vals, int E,
                            const float* __restrict__ prev,
                            float* __restrict__ agg)
{
    int t = blockIdx.x * blockDim.x + threadIdx.x;
    int e = t >> 4;
    int lane = t & 15;
    if (e >= E) return;
    int row = __ldg(rows + e);
    int col = __ldg(cols + e);
    float v = __ldg(vals + e);
    float4 p = *(const float4*)(prev + (size_t)col * 64 + lane * 4);
    float4 q = make_float4(p.x * v, p.y * v, p.z * v, p.w * v);
    red_add_v4(agg + (size_t)row * 64 + lane * 4, q);
}

// ---------------------------------------------------------------------------
// Combine (layers 0/1: mask == all ones): sum += agg; zero the other buffer
// ---------------------------------------------------------------------------
__global__ void combine_kernel(const float* __restrict__ agg,
                               float* __restrict__ sum,
                               float* __restrict__ zbuf, int n4)
{
    int i = blockIdx.x * blockDim.x + threadIdx.x;
    if (i >= n4) return;
    float4 a = ((const float4*)agg)[i];
    float4 s = ((float4*)sum)[i];
    s.x += a.x; s.y += a.y; s.z += a.z; s.w += a.w;
    ((float4*)sum)[i] = s;
    ((float4*)zbuf)[i] = make_float4(0.f, 0.f, 0.f, 0.f);
}

// ---------------------------------------------------------------------------
// Combine layer 2 (masked): sum += mask ? agg : prev
// ---------------------------------------------------------------------------
__global__ void combine2_kernel(const float* __restrict__ agg,
                                const float* __restrict__ prev,
                                float* __restrict__ sum,
                                unsigned long long mask, int n4)
{
    int i = blockIdx.x * blockDim.x + threadIdx.x;
    if (i >= n4) return;
    int d = (i * 4) & 63;
    float4 a = ((const float4*)agg)[i];
    float4 p = ((const float4*)prev)[i];
    float4 s = ((float4*)sum)[i];
    s.x += ((mask >> (d + 0)) & 1ull) ? a.x : p.x;
    s.y += ((mask >> (d + 1)) & 1ull) ? a.y : p.y;
    s.z += ((mask >> (d + 2)) & 1ull) ? a.z : p.z;
    s.w += ((mask >> (d + 3)) & 1ull) ? a.w : p.w;
    ((float4*)sum)[i] = s;
}

// ---------------------------------------------------------------------------
// Final: out[b] = (sum[u] . sum[U+i]) / R^2     (one warp per pair)
// ---------------------------------------------------------------------------
__global__ void final_kernel(const int* __restrict__ users,
                             const int* __restrict__ items,
                             const float* __restrict__ sum,
                             int U, float invR2,
                             float* __restrict__ out, int B)
{
    int b = blockIdx.x * (blockDim.x >> 5) + (threadIdx.x >> 5);
    int lane = threadIdx.x & 31;
    if (b >= B) return;
    int u = users[b];
    int it = items[b];
    const float* pu = sum + (size_t)u * 64;
    const float* pi = sum + ((size_t)U + it) * 64;
    float acc = pu[lane] * pi[lane] + pu[lane + 32] * pi[lane + 32];
    #pragma unroll
    for (int off = 16; off; off >>= 1)
        acc += __shfl_xor_sync(0xffffffffu, acc, off);
    if (lane == 0) out[b] = acc * invR2;
}

// ---------------------------------------------------------------------------
// Host: numpy MT19937 RandomState(2).permutation(64) -> layer-2 mask bits
// ---------------------------------------------------------------------------
static unsigned long long compute_layer2_mask(int d)
{
    const int NN = 624, MM = 397;
    unsigned int key[624];
    unsigned int s = 2u;   // seed = layer = 2
    for (int i = 0; i < NN; i++) {
        key[i] = s;
        s = 1812433253u * (s ^ (s >> 30)) + (unsigned)i + 1u;
    }
    int pos = NN;
    auto next_u32 = [&]() -> unsigned int {
        if (pos == NN) {
            for (int i = 0; i < NN; i++) {
                unsigned int y = (key[i] & 0x80000000u) |
                                 (key[(i + 1) % NN] & 0x7fffffffu);
                unsigned int v = key[(i + MM) % NN] ^ (y >> 1);
                if (y & 1u) v ^= 0x9908b0dfu;
                key[i] = v;
            }
            pos = 0;
        }
        unsigned int y = key[pos++];
        y ^= y >> 11;
        y ^= (y << 7)  & 0x9d2c5680u;
        y ^= (y << 15) & 0xefc60000u;
        y ^= y >> 18;
        return y;
    };
    int perm[64];
    for (int i = 0; i < d; i++) perm[i] = i;
    for (int i = d - 1; i > 0; i--) {
        unsigned int m = (unsigned)i;
        m |= m >> 1; m |= m >> 2; m |= m >> 4; m |= m >> 8; m |= m >> 16;
        unsigned int j;
        do { j = next_u32() & m; } while (j > (unsigned)i);
        int t = perm[i]; perm[i] = perm[j]; perm[j] = t;
    }
    double ratio = 1.0 - log(1.0 / 2.0 + 1.0);
    int nm = (int)(ratio * d);
    unsigned long long bits = 0ull;
    for (int i = 0; i < d; i++)
        if (perm[i] >= nm) bits |= (1ull << i);
    return bits;
}

// ---------------------------------------------------------------------------
extern "C" void kernel_launch(void* const* d_in, const int* in_sizes, int n_in,
                              void* d_out, int out_size)
{
    const int*   users      = (const int*)  d_in[0];
    const int*   items      = (const int*)  d_in[1];
    const float* user_emb   = (const float*)d_in[2];
    const float* item_emb   = (const float*)d_in[3];
    const float* rating_emb = (const float*)d_in[4];
    const float* W1         = (const float*)d_in[5];
    const float* b1         = (const float*)d_in[6];
    const float* W2         = (const float*)d_in[7];
    const float* b2         = (const float*)d_in[8];
    const int*   rows       = (const int*)  d_in[9];
    const int*   cols       = (const int*)  d_in[10];
    const float* vals       = (const float*)d_in[11];

    const int B = in_sizes[0];
    const int U = in_sizes[2] / D;
    const int I = in_sizes[3] / D;
    const int N = U + I;
    const int R = in_sizes[4] / D;
    const int E = in_sizes[9] / R;

    float *buf0, *buf1, *sumb;
    cudaGetSymbolAddress((void**)&buf0, g_buf0);
    cudaGetSymbolAddress((void**)&buf1, g_buf1);
    cudaGetSymbolAddress((void**)&sumb, g_sum);

    const unsigned long long mask2 = compute_layer2_mask(D);

    const int smem_bytes = (64 * 132 + 64 * 64 + 64 * 64 + 64 + 64) * 4;
    cudaFuncSetAttribute(mlp_kernel, cudaFuncAttributeMaxDynamicSharedMemorySize,
                         smem_bytes);

    const int mlp_grid  = (N + MLP_ROWS - 1) / MLP_ROWS;
    const int n4        = N * (D / 4);
    const int comb_grid = (n4 + 255) / 256;
    const long long spmm_threads = (long long)E * 16;
    const int spmm_grid = (int)((spmm_threads + 255) / 256);

    for (int r = 0; r < R; r++) {
        const int* er = rows + (size_t)r * E;
        const int* ec = cols + (size_t)r * E;
        const float* ev = vals + (size_t)r * E;

        mlp_kernel<<<mlp_grid, MLP_THREADS, smem_bytes>>>(
            user_emb, item_emb, U, N, W1, b1, W2, b2, rating_emb,
            r, (r == 0) ? 1 : 0, buf0, buf1, sumb);

        // layer 0: prev=buf0 -> agg=buf1 ; combine zeroes buf0
        spmm_kernel<<<spmm_grid, 256>>>(er, ec, ev, E, buf0, buf1);
        combine_kernel<<<comb_grid, 256>>>(buf1, sumb, buf0, n4);

        // layer 1: prev=buf1 -> agg=buf0 ; combine zeroes buf1
        spmm_kernel<<<spmm_grid, 256>>>(er, ec, ev, E, buf1, buf0);
        combine_kernel<<<comb_grid, 256>>>(buf0, sumb, buf1, n4);

        // layer 2: prev=buf0 -> agg=buf1 ; masked combine
        spmm_kernel<<<spmm_grid, 256>>>(er, ec, ev, E, buf0, buf1);
        combine2_kernel<<<comb_grid, 256>>>(buf1, buf0, sumb, mask2, n4);
    }

    const float invR2 = 1.0f / (float)(R * R);
    const int warps_per_block = 256 / 32;
    const int fin_grid = (B + warps_per_block - 1) / warps_per_block;
    final_kernel<<<fin_grid, 256>>>(users, items, sumb, U, invR2,
                                    (float*)d_out, B);
}

// round 2
// speedup vs baseline: 1.6230x; 1.6230x over previous
#include <cuda_runtime.h>
#include <cuda_bf16.h>
#include <math.h>
#include <stdint.h>

// ---------------------------------------------------------------------------
// DCGCN: U=I=50000 (N=100000), R=5, D=64, E=1e6/rating, B=8192. Output f32[B].
// Strategy: per-launch CSR build (atomic-free SpMM), fused combine epilogues.
// ---------------------------------------------------------------------------

#define D 64
#define MAXN 100352
#define MAXR 5
#define MAXE 1048576
#define MLP_ROWS 128
#define MLP_THREADS 256

__device__ float g_buf0[(size_t)MAXN * D];
__device__ float g_buf1[(size_t)MAXN * D];
__device__ float g_sum [(size_t)MAXN * D];
__device__ int   g_deg  [MAXR * MAXN];        // reused as scatter cursor
__device__ int   g_start[MAXR * MAXN + 1];
__device__ int   g_bsum [2048];
__device__ int2  g_edges[(size_t)MAXR * MAXE]; // packed {col, f32 val}

// ---------------------------------------------------------------------------
// CSR build kernels
// ---------------------------------------------------------------------------
__global__ void zero_deg_kernel(int* __restrict__ deg, int tot)
{
    int i = blockIdx.x * blockDim.x + threadIdx.x;
    if (i < tot) deg[i] = 0;
}

__global__ void hist_kernel(const int* __restrict__ rows, int E, int N,
                            int* __restrict__ deg, int tot)
{
    int i = blockIdx.x * blockDim.x + threadIdx.x;
    if (i >= tot) return;
    int r = i / E;
    atomicAdd(&deg[r * N + rows[i]], 1);
}

// block-level exclusive scan (1024/block); bsum[b] = block total
__global__ void __launch_bounds__(1024) scanA_kernel(
    const int* __restrict__ deg, int tot,
    int* __restrict__ out, int* __restrict__ bsum)
{
    __shared__ int sm[1024];
    int i = blockIdx.x * 1024 + threadIdx.x;
    int v = (i < tot) ? deg[i] : 0;
    sm[threadIdx.x] = v;
    __syncthreads();
    #pragma unroll
    for (int o = 1; o < 1024; o <<= 1) {
        int t = (threadIdx.x >= o) ? sm[threadIdx.x - o] : 0;
        __syncthreads();
        sm[threadIdx.x] += t;
        __syncthreads();
    }
    if (i < tot) out[i] = sm[threadIdx.x] - v;      // exclusive within block
    if (threadIdx.x == 1023) bsum[blockIdx.x] = sm[1023];
}

// single block: exclusive scan of up to 2048 block sums
__global__ void __launch_bounds__(1024) scanB_kernel(int* __restrict__ bsum, int nblk)
{
    __shared__ int sm[2048];
    for (int i = threadIdx.x; i < 2048; i += 1024)
        sm[i] = (i < nblk) ? bsum[i] : 0;
    __syncthreads();
    for (int o = 1; o < 2048; o <<= 1) {
        int t0 = (threadIdx.x >= o) ? sm[threadIdx.x - o] : 0;
        int i1 = threadIdx.x + 1024;
        int t1 = (i1 >= o) ? sm[i1 - o] : 0;
        __syncthreads();
        sm[threadIdx.x] += t0;
        sm[i1] += t1;
        __syncthreads();
    }
    for (int i = threadIdx.x; i < nblk; i += 1024) {
        int incl = sm[i];
        int own  = (i < nblk) ? 0 : 0;
        (void)own;
        bsum[i] = incl;   // inclusive for now; adjust below
    }
    __syncthreads();
    // convert to exclusive: bsum[i] = incl[i-1]
    int v0 = (threadIdx.x < nblk) ? ((threadIdx.x == 0) ? 0 : sm[threadIdx.x - 1]) : 0;
    int i1 = threadIdx.x + 1024;
    int v1 = (i1 < nblk) ? sm[i1 - 1] : 0;
    __syncthreads();
    if (threadIdx.x < nblk) bsum[threadIdx.x] = v0;
    if (i1 < nblk) bsum[i1] = v1;
}

// add block offsets; init cursor; write sentinel
__global__ void __launch_bounds__(1024) scanC_kernel(
    int* __restrict__ start, int* __restrict__ cursor,
    const int* __restrict__ bsum, int tot, int totE)
{
    int i = blockIdx.x * 1024 + threadIdx.x;
    if (i < tot) {
        int v = start[i] + bsum[blockIdx.x];
        start[i]  = v;
        cursor[i] = v;
    }
    if (i == 0) start[tot] = totE;
}

__global__ void scatter_kernel(const int* __restrict__ rows,
                               const int* __restrict__ cols,
                               const float* __restrict__ vals,
                               int E, int N, int* __restrict__ cursor,
                               int2* __restrict__ edges, int tot)
{
    int i = blockIdx.x * blockDim.x + threadIdx.x;
    if (i >= tot) return;
    int r = i / E;
    int pos = atomicAdd(&cursor[r * N + rows[i]], 1);
    edges[pos] = make_int2(cols[i], __float_as_int(vals[i]));
}

// ---------------------------------------------------------------------------
// MLP kernel: h = leaky_relu(base @ W1a + c1) @ W2 + b2
//   c1 = b1[r] + rating_emb[r] @ W1[r][64:128]
// Writes: prevbuf = h ; sum (+)= h
// ---------------------------------------------------------------------------
__global__ void __launch_bounds__(MLP_THREADS) mlp_kernel(
    const float* __restrict__ user_emb, const float* __restrict__ item_emb,
    int U, int N,
    const float* __restrict__ W1, const float* __restrict__ b1,
    const float* __restrict__ W2, const float* __restrict__ b2,
    const float* __restrict__ rating_emb,
    int r, int first,
    float* __restrict__ prevbuf, float* __restrict__ sumbuf)
{
    extern __shared__ float smem[];
    float* xs  = smem;                   // 64*132
    float* W1s = xs + 64 * 132;
    float* W2s = W1s + 64 * 64;
    float* c1s = W2s + 64 * 64;
    float* b2s = c1s + 64;

    const float* W1r = W1 + (size_t)r * 128 * 64;
    const float* W2r = W2 + (size_t)r * 64 * 64;
    const int tid = threadIdx.x;
    const int row0 = blockIdx.x * MLP_ROWS;

    for (int i = tid; i < 1024; i += MLP_THREADS) {
        ((float4*)W1s)[i] = ((const float4*)W1r)[i];
        ((float4*)W2s)[i] = ((const float4*)W2r)[i];
    }
    if (tid < 64) {
        float c = b1[r * 64 + tid];
        #pragma unroll 8
        for (int k = 0; k < 64; k++)
            c += rating_emb[r * 64 + k] * W1r[(64 + k) * 64 + tid];
        c1s[tid] = c;
        b2s[tid] = b2[r * 64 + tid];
    }
    for (int i = tid; i < MLP_ROWS * 16; i += MLP_THREADS) {
        int rr = i >> 4;
        int c4 = i & 15;
        int row = row0 + rr;
        float4 v = make_float4(0.f, 0.f, 0.f, 0.f);
        if (row < N) {
            const float* src = (row < U) ? (user_emb + (size_t)row * 64)
                                         : (item_emb + (size_t)(row - U) * 64);
            v = ((const float4*)src)[c4];
        }
        xs[(4 * c4 + 0) * 132 + rr] = v.x;
        xs[(4 * c4 + 1) * 132 + rr] = v.y;
        xs[(4 * c4 + 2) * 132 + rr] = v.z;
        xs[(4 * c4 + 3) * 132 + rr] = v.w;
    }
    __syncthreads();

    const int rg = tid >> 4;
    const int cg = tid & 15;

    float acc[8][4];
    #pragma unroll
    for (int a = 0; a < 8; a++)
        #pragma unroll
        for (int bb = 0; bb < 4; bb++) acc[a][bb] = 0.f;

    #pragma unroll 8
    for (int k = 0; k < 64; k++) {
        float4 x0 = *(const float4*)(xs + k * 132 + rg * 8);
        float4 x1 = *(const float4*)(xs + k * 132 + rg * 8 + 4);
        float4 w  = *(const float4*)(W1s + k * 64 + cg * 4);
        float xv[8] = {x0.x, x0.y, x0.z, x0.w, x1.x, x1.y, x1.z, x1.w};
        #pragma unroll
        for (int a = 0; a < 8; a++) {
            acc[a][0] += xv[a] * w.x;
            acc[a][1] += xv[a] * w.y;
            acc[a][2] += xv[a] * w.z;
            acc[a][3] += xv[a] * w.w;
        }
    }
    __syncthreads();

    #pragma unroll
    for (int bb = 0; bb < 4; bb++) {
        float c = c1s[cg * 4 + bb];
        #pragma unroll
        for (int a = 0; a < 8; a++) {
            float v = acc[a][bb] + c;
            v = (v > 0.f) ? v : 0.01f * v;
            xs[(cg * 4 + bb) * 132 + rg * 8 + a] = v;
        }
    }
    __syncthreads();

    #pragma unroll
    for (int a = 0; a < 8; a++)
        #pragma unroll
        for (int bb = 0; bb < 4; bb++) acc[a][bb] = 0.f;

    #pragma unroll 8
    for (int k = 0; k < 64; k++) {
        float4 x0 = *(const float4*)(xs + k * 132 + rg * 8);
        float4 x1 = *(const float4*)(xs + k * 132 + rg * 8 + 4);
        float4 w  = *(const float4*)(W2s + k * 64 + cg * 4);
        float xv[8] = {x0.x, x0.y, x0.z, x0.w, x1.x, x1.y, x1.z, x1.w};
        #pragma unroll
        for (int a = 0; a < 8; a++) {
            acc[a][0] += xv[a] * w.x;
            acc[a][1] += xv[a] * w.y;
            acc[a][2] += xv[a] * w.z;
            acc[a][3] += xv[a] * w.w;
        }
    }

    float4 bv = *(const float4*)(b2s + cg * 4);
    #pragma unroll
    for (int a = 0; a < 8; a++) {
        int row = row0 + rg * 8 + a;
        if (row < N) {
            float4 o = make_float4(acc[a][0] + bv.x, acc[a][1] + bv.y,
                                   acc[a][2] + bv.z, acc[a][3] + bv.w);
            size_t off = (size_t)row * 64 + cg * 4;
            *(float4*)(prevbuf + off) = o;
            if (first) {
                *(float4*)(sumbuf + off) = o;
            } else {
                float4 s = *(float4*)(sumbuf + off);
                s.x += o.x; s.y += o.y; s.z += o.z; s.w += o.w;
                *(float4*)(sumbuf + off) = s;
            }
        }
    }
}

// ---------------------------------------------------------------------------
// CSR SpMM + fused combine. 16 threads/row, float4 per thread.
// layer2=0: next[row] = acc; sum[row] += acc
// layer2=1: sum[row] += mask ? acc : prev[row]
// ---------------------------------------------------------------------------
__global__ void __launch_bounds__(256) spmm_csr_kernel(
    const int* __restrict__ start, const int2* __restrict__ edges,
    const float* __restrict__ prev, float* __restrict__ next,
    float* __restrict__ sum, int rbase, int N,
    int layer2, unsigned long long mask)
{
    int row  = blockIdx.x * (blockDim.x >> 4) + (threadIdx.x >> 4);
    int lane = threadIdx.x & 15;
    if (row >= N) return;

    int s = __ldg(start + rbase + row);
    int e = __ldg(start + rbase + row + 1);

    float4 acc = make_float4(0.f, 0.f, 0.f, 0.f);
    int j = s;
    for (; j + 1 < e; j += 2) {
        int2 e0 = __ldg(edges + j);
        int2 e1 = __ldg(edges + j + 1);
        float4 p0 = *(const float4*)(prev + (size_t)e0.x * 64 + lane * 4);
        float4 p1 = *(const float4*)(prev + (size_t)e1.x * 64 + lane * 4);
        float v0 = __int_as_float(e0.y);
        float v1 = __int_as_float(e1.y);
        acc.x += v0 * p0.x; acc.y += v0 * p0.y;
        acc.z += v0 * p0.z; acc.w += v0 * p0.w;
        acc.x += v1 * p1.x; acc.y += v1 * p1.y;
        acc.z += v1 * p1.z; acc.w += v1 * p1.w;
    }
    if (j < e) {
        int2 e0 = __ldg(edges + j);
        float4 p0 = *(const float4*)(prev + (size_t)e0.x * 64 + lane * 4);
        float v0 = __int_as_float(e0.y);
        acc.x += v0 * p0.x; acc.y += v0 * p0.y;
        acc.z += v0 * p0.z; acc.w += v0 * p0.w;
    }

    size_t off = (size_t)row * 64 + lane * 4;
    if (!layer2) {
        *(float4*)(next + off) = acc;
        float4 sv = *(float4*)(sum + off);
        sv.x += acc.x; sv.y += acc.y; sv.z += acc.z; sv.w += acc.w;
        *(float4*)(sum + off) = sv;
    } else {
        float4 pv = *(const float4*)(prev + off);
        int d = lane * 4;
        float4 sv = *(float4*)(sum + off);
        sv.x += ((mask >> (d + 0)) & 1ull) ? acc.x : pv.x;
        sv.y += ((mask >> (d + 1)) & 1ull) ? acc.y : pv.y;
        sv.z += ((mask >> (d + 2)) & 1ull) ? acc.z : pv.z;
        sv.w += ((mask >> (d + 3)) & 1ull) ? acc.w : pv.w;
        *(float4*)(sum + off) = sv;
    }
}

// ---------------------------------------------------------------------------
// Final: out[b] = (sum[u] . sum[U+i]) / R^2
// ---------------------------------------------------------------------------
__global__ void final_kernel(const int* __restrict__ users,
                             const int* __restrict__ items,
                             const float* __restrict__ sum,
                             int U, float invR2,
                             float* __restrict__ out, int B)
{
    int b = blockIdx.x * (blockDim.x >> 5) + (threadIdx.x >> 5);
    int lane = threadIdx.x & 31;
    if (b >= B) return;
    int u = users[b];
    int it = items[b];
    const float* pu = sum + (size_t)u * 64;
    const float* pi = sum + ((size_t)U + it) * 64;
    float acc = pu[lane] * pi[lane] + pu[lane + 32] * pi[lane + 32];
    #pragma unroll
    for (int off = 16; off; off >>= 1)
        acc += __shfl_xor_sync(0xffffffffu, acc, off);
    if (lane == 0) out[b] = acc * invR2;
}

// ---------------------------------------------------------------------------
// Host: numpy MT19937 RandomState(2).permutation(64) -> layer-2 mask bits
// ---------------------------------------------------------------------------
static unsigned long long compute_layer2_mask(int d)
{
    const int NN = 624, MM = 397;
    unsigned int key[624];
    unsigned int s = 2u;
    for (int i = 0; i < NN; i++) {
        key[i] = s;
        s = 1812433253u * (s ^ (s >> 30)) + (unsigned)i + 1u;
    }
    int pos = NN;
    auto next_u32 = [&]() -> unsigned int {
        if (pos == NN) {
            for (int i = 0; i < NN; i++) {
                unsigned int y = (key[i] & 0x80000000u) |
                                 (key[(i + 1) % NN] & 0x7fffffffu);
                unsigned int v = key[(i + MM) % NN] ^ (y >> 1);
                if (y & 1u) v ^= 0x9908b0dfu;
                key[i] = v;
            }
            pos = 0;
        }
        unsigned int y = key[pos++];
        y ^= y >> 11;
        y ^= (y << 7)  & 0x9d2c5680u;
        y ^= (y << 15) & 0xefc60000u;
        y ^= y >> 18;
        return y;
    };
    int perm[64];
    for (int i = 0; i < d; i++) perm[i] = i;
    for (int i = d - 1; i > 0; i--) {
        unsigned int m = (unsigned)i;
        m |= m >> 1; m |= m >> 2; m |= m >> 4; m |= m >> 8; m |= m >> 16;
        unsigned int j;
        do { j = next_u32() & m; } while (j > (unsigned)i);
        int t = perm[i]; perm[i] = perm[j]; perm[j] = t;
    }
    double ratio = 1.0 - log(1.0 / 2.0 + 1.0);
    int nm = (int)(ratio * d);
    unsigned long long bits = 0ull;
    for (int i = 0; i < d; i++)
        if (perm[i] >= nm) bits |= (1ull << i);
    return bits;
}

// ---------------------------------------------------------------------------
extern "C" void kernel_launch(void* const* d_in, const int* in_sizes, int n_in,
                              void* d_out, int out_size)
{
    const int*   users      = (const int*)  d_in[0];
    const int*   items      = (const int*)  d_in[1];
    const float* user_emb   = (const float*)d_in[2];
    const float* item_emb   = (const float*)d_in[3];
    const float* rating_emb = (const float*)d_in[4];
    const float* W1         = (const float*)d_in[5];
    const float* b1         = (const float*)d_in[6];
    const float* W2         = (const float*)d_in[7];
    const float* b2         = (const float*)d_in[8];
    const int*   rows       = (const int*)  d_in[9];
    const int*   cols       = (const int*)  d_in[10];
    const float* vals       = (const float*)d_in[11];

    const int B = in_sizes[0];
    const int U = in_sizes[2] / D;
    const int I = in_sizes[3] / D;
    const int N = U + I;
    const int R = in_sizes[4] / D;
    const int E = in_sizes[9] / R;

    float *buf0, *buf1, *sumb;
    int *deg, *startp, *bsum;
    int2 *edges;
    cudaGetSymbolAddress((void**)&buf0,  g_buf0);
    cudaGetSymbolAddress((void**)&buf1,  g_buf1);
    cudaGetSymbolAddress((void**)&sumb,  g_sum);
    cudaGetSymbolAddress((void**)&deg,   g_deg);
    cudaGetSymbolAddress((void**)&startp,g_start);
    cudaGetSymbolAddress((void**)&bsum,  g_bsum);
    cudaGetSymbolAddress((void**)&edges, g_edges);

    const unsigned long long mask2 = compute_layer2_mask(D);

    // ---- CSR build (all ratings at once) ----
    const int totRN = R * N;
    const int totRE = R * E;
    const int nblk  = (totRN + 1023) / 1024;

    zero_deg_kernel<<<(totRN + 255) / 256, 256>>>(deg, totRN);
    hist_kernel<<<(totRE + 255) / 256, 256>>>(rows, E, N, deg, totRE);
    scanA_kernel<<<nblk, 1024>>>(deg, totRN, startp, bsum);
    scanB_kernel<<<1, 1024>>>(bsum, nblk);
    scanC_kernel<<<nblk, 1024>>>(startp, deg /*cursor*/, bsum, totRN, totRE);
    scatter_kernel<<<(totRE + 255) / 256, 256>>>(rows, cols, vals, E, N,
                                                 deg, edges, totRE);

    // ---- per-rating pipeline ----
    const int smem_bytes = (64 * 132 + 64 * 64 + 64 * 64 + 64 + 64) * 4;
    cudaFuncSetAttribute(mlp_kernel, cudaFuncAttributeMaxDynamicSharedMemorySize,
                         smem_bytes);
    const int mlp_grid  = (N + MLP_ROWS - 1) / MLP_ROWS;
    const int rows_per_blk = 256 / 16;
    const int spmm_grid = (N + rows_per_blk - 1) / rows_per_blk;

    for (int r = 0; r < R; r++) {
        mlp_kernel<<<mlp_grid, MLP_THREADS, smem_bytes>>>(
            user_emb, item_emb, U, N, W1, b1, W2, b2, rating_emb,
            r, (r == 0) ? 1 : 0, buf0, sumb);

        int rbase = r * N;
        // layer 0: buf0 -> buf1
        spmm_csr_kernel<<<spmm_grid, 256>>>(startp, edges, buf0, buf1, sumb,
                                            rbase, N, 0, 0ull);
        // layer 1: buf1 -> buf0
        spmm_csr_kernel<<<spmm_grid, 256>>>(startp, edges, buf1, buf0, sumb,
                                            rbase, N, 0, 0ull);
        // layer 2: buf0 -> (masked into sum)
        spmm_csr_kernel<<<spmm_grid, 256>>>(startp, edges, buf0, buf1, sumb,
                                            rbase, N, 1, mask2);
    }

    const float invR2 = 1.0f / (float)(R * R);
    const int warps_per_block = 256 / 32;
    const int fin_grid = (B + warps_per_block - 1) / warps_per_block;
    final_kernel<<<fin_grid, 256>>>(users, items, sumb, U, invR2,
                                    (float*)d_out, B);
}

// round 3
// speedup vs baseline: 1.8869x; 1.1626x over previous
#include <cuda_runtime.h>
#include <cuda_fp16.h>
#include <math.h>
#include <stdint.h>

// ---------------------------------------------------------------------------
// DCGCN: U=I=50000 (N=100000), R=5, D=64, E=1e6/rating, B=8192. Output f32[B].
// R3: fp16 activation buffers (half gather traffic), fused sum epilogues,
//     f32x2 packed-FMA MLP.
// ---------------------------------------------------------------------------

#define D 64
#define MAXN 100352
#define MAXR 5
#define MAXE 1048576
#define MLP_ROWS 128
#define MLP_THREADS 256

__device__ __half g_bufA[(size_t)MAXN * D];
__device__ __half g_bufB[(size_t)MAXN * D];
__device__ float  g_sum [(size_t)MAXN * D];
__device__ int    g_deg  [MAXR * MAXN];
__device__ int    g_start[MAXR * MAXN + 1];
__device__ int    g_bsum [2048];
__device__ int2   g_edges[(size_t)MAXR * MAXE];

#define FMA_F32X2(d, a, b, c) \
    asm("fma.rn.f32x2 %0, %1, %2, %3;" : "=l"(d) : "l"(a), "l"(b), "l"(c))
#define SPLAT_F32X2(out, f) \
    asm("mov.b64 %0, {%1, %1};" : "=l"(out) : "r"(__float_as_uint(f)))

// ---------------------------------------------------------------------------
// CSR build
// ---------------------------------------------------------------------------
__global__ void zero_deg_kernel(int* __restrict__ deg, int tot)
{
    int i = blockIdx.x * blockDim.x + threadIdx.x;
    if (i < tot) deg[i] = 0;
}

__global__ void hist_kernel(const int* __restrict__ rows, int E, int N,
                            int* __restrict__ deg, int tot)
{
    int i = blockIdx.x * blockDim.x + threadIdx.x;
    if (i >= tot) return;
    int r = i / E;
    atomicAdd(&deg[r * N + rows[i]], 1);
}

__global__ void __launch_bounds__(1024) scanA_kernel(
    const int* __restrict__ deg, int tot,
    int* __restrict__ out, int* __restrict__ bsum)
{
    __shared__ int sm[1024];
    int i = blockIdx.x * 1024 + threadIdx.x;
    int v = (i < tot) ? deg[i] : 0;
    sm[threadIdx.x] = v;
    __syncthreads();
    #pragma unroll
    for (int o = 1; o < 1024; o <<= 1) {
        int t = (threadIdx.x >= o) ? sm[threadIdx.x - o] : 0;
        __syncthreads();
        sm[threadIdx.x] += t;
        __syncthreads();
    }
    if (i < tot) out[i] = sm[threadIdx.x] - v;
    if (threadIdx.x == 1023) bsum[blockIdx.x] = sm[1023];
}

__global__ void __launch_bounds__(1024) scanB_kernel(int* __restrict__ bsum, int nblk)
{
    __shared__ int sm[2048];
    for (int i = threadIdx.x; i < 2048; i += 1024)
        sm[i] = (i < nblk) ? bsum[i] : 0;
    __syncthreads();
    for (int o = 1; o < 2048; o <<= 1) {
        int t0 = (threadIdx.x >= o) ? sm[threadIdx.x - o] : 0;
        int i1 = threadIdx.x + 1024;
        int t1 = (i1 >= o) ? sm[i1 - o] : 0;
        __syncthreads();
        sm[threadIdx.x] += t0;
        sm[i1] += t1;
        __syncthreads();
    }
    int v0 = (threadIdx.x < nblk) ? ((threadIdx.x == 0) ? 0 : sm[threadIdx.x - 1]) : 0;
    int i1 = threadIdx.x + 1024;
    int v1 = (i1 < nblk) ? sm[i1 - 1] : 0;
    __syncthreads();
    if (threadIdx.x < nblk) bsum[threadIdx.x] = v0;
    if (i1 < nblk) bsum[i1] = v1;
}

__global__ void __launch_bounds__(1024) scanC_kernel(
    int* __restrict__ start, int* __restrict__ cursor,
    const int* __restrict__ bsum, int tot, int totE)
{
    int i = blockIdx.x * 1024 + threadIdx.x;
    if (i < tot) {
        int v = start[i] + bsum[blockIdx.x];
        start[i]  = v;
        cursor[i] = v;
    }
    if (i == 0) start[tot] = totE;
}

__global__ void scatter_kernel(const int* __restrict__ rows,
                               const int* __restrict__ cols,
                               const float* __restrict__ vals,
                               int E, int N, int* __restrict__ cursor,
                               int2* __restrict__ edges, int tot)
{
    int i = blockIdx.x * blockDim.x + threadIdx.x;
    if (i >= tot) return;
    int r = i / E;
    int pos = atomicAdd(&cursor[r * N + rows[i]], 1);
    edges[pos] = make_int2(cols[i], __float_as_int(vals[i]));
}

// ---------------------------------------------------------------------------
// MLP: h = leaky_relu(base @ W1a + c1) @ W2 + b2 ;  prevbuf(half) = h
// f32x2 packed FMA inner loops.
// ---------------------------------------------------------------------------
__global__ void __launch_bounds__(MLP_THREADS) mlp_kernel(
    const float* __restrict__ user_emb, const float* __restrict__ item_emb,
    int U, int N,
    const float* __restrict__ W1, const float* __restrict__ b1,
    const float* __restrict__ W2, const float* __restrict__ b2,
    const float* __restrict__ rating_emb,
    int r, __half* __restrict__ prevbuf)
{
    extern __shared__ float smem[];
    float* xs  = smem;                   // 64*132
    float* W1s = xs + 64 * 132;
    float* W2s = W1s + 64 * 64;
    float* c1s = W2s + 64 * 64;
    float* b2s = c1s + 64;

    const float* W1r = W1 + (size_t)r * 128 * 64;
    const float* W2r = W2 + (size_t)r * 64 * 64;
    const int tid = threadIdx.x;
    const int row0 = blockIdx.x * MLP_ROWS;

    for (int i = tid; i < 1024; i += MLP_THREADS) {
        ((float4*)W1s)[i] = ((const float4*)W1r)[i];
        ((float4*)W2s)[i] = ((const float4*)W2r)[i];
    }
    if (tid < 64) {
        float c = b1[r * 64 + tid];
        #pragma unroll 8
        for (int k = 0; k < 64; k++)
            c += rating_emb[r * 64 + k] * W1r[(64 + k) * 64 + tid];
        c1s[tid] = c;
        b2s[tid] = b2[r * 64 + tid];
    }
    for (int i = tid; i < MLP_ROWS * 16; i += MLP_THREADS) {
        int rr = i >> 4;
        int c4 = i & 15;
        int row = row0 + rr;
        float4 v = make_float4(0.f, 0.f, 0.f, 0.f);
        if (row < N) {
            const float* src = (row < U) ? (user_emb + (size_t)row * 64)
                                         : (item_emb + (size_t)(row - U) * 64);
            v = ((const float4*)src)[c4];
        }
        xs[(4 * c4 + 0) * 132 + rr] = v.x;
        xs[(4 * c4 + 1) * 132 + rr] = v.y;
        xs[(4 * c4 + 2) * 132 + rr] = v.z;
        xs[(4 * c4 + 3) * 132 + rr] = v.w;
    }
    __syncthreads();

    const int rg = tid >> 4;   // 8 rows each
    const int cg = tid & 15;   // 4 cols each

    // accp[c][p]: f32x2 pair over rows (2p, 2p+1) for column cg*4+c
    unsigned long long accp[4][4];

    // ---- layer 1 ----
    #pragma unroll
    for (int c = 0; c < 4; c++)
        #pragma unroll
        for (int p = 0; p < 4; p++) accp[c][p] = 0ull;

    #pragma unroll 4
    for (int k = 0; k < 64; k++) {
        float4 x0 = *(const float4*)(xs + k * 132 + rg * 8);
        float4 x1 = *(const float4*)(xs + k * 132 + rg * 8 + 4);
        float4 w  = *(const float4*)(W1s + k * 64 + cg * 4);
        unsigned long long xp[4];
        xp[0] = ((const unsigned long long*)&x0)[0];
        xp[1] = ((const unsigned long long*)&x0)[1];
        xp[2] = ((const unsigned long long*)&x1)[0];
        xp[3] = ((const unsigned long long*)&x1)[1];
        unsigned long long ws[4];
        SPLAT_F32X2(ws[0], w.x);
        SPLAT_F32X2(ws[1], w.y);
        SPLAT_F32X2(ws[2], w.z);
        SPLAT_F32X2(ws[3], w.w);
        #pragma unroll
        for (int c = 0; c < 4; c++)
            #pragma unroll
            for (int p = 0; p < 4; p++)
                FMA_F32X2(accp[c][p], xp[p], ws[c], accp[c][p]);
    }
    __syncthreads();

    // leaky_relu(acc + c1) -> xs (transposed)
    #pragma unroll
    for (int c = 0; c < 4; c++) {
        float cc = c1s[cg * 4 + c];
        #pragma unroll
        for (int p = 0; p < 4; p++) {
            float2 f = *(float2*)&accp[c][p];
            float v0 = f.x + cc; v0 = (v0 > 0.f) ? v0 : 0.01f * v0;
            float v1 = f.y + cc; v1 = (v1 > 0.f) ? v1 : 0.01f * v1;
            xs[(cg * 4 + c) * 132 + rg * 8 + 2 * p]     = v0;
            xs[(cg * 4 + c) * 132 + rg * 8 + 2 * p + 1] = v1;
        }
    }
    __syncthreads();

    // ---- layer 2 ----
    #pragma unroll
    for (int c = 0; c < 4; c++)
        #pragma unroll
        for (int p = 0; p < 4; p++) accp[c][p] = 0ull;

    #pragma unroll 4
    for (int k = 0; k < 64; k++) {
        float4 x0 = *(const float4*)(xs + k * 132 + rg * 8);
        float4 x1 = *(const float4*)(xs + k * 132 + rg * 8 + 4);
        float4 w  = *(const float4*)(W2s + k * 64 + cg * 4);
        unsigned long long xp[4];
        xp[0] = ((const unsigned long long*)&x0)[0];
        xp[1] = ((const unsigned long long*)&x0)[1];
        xp[2] = ((const unsigned long long*)&x1)[0];
        xp[3] = ((const unsigned long long*)&x1)[1];
        unsigned long long ws[4];
        SPLAT_F32X2(ws[0], w.x);
        SPLAT_F32X2(ws[1], w.y);
        SPLAT_F32X2(ws[2], w.z);
        SPLAT_F32X2(ws[3], w.w);
        #pragma unroll
        for (int c = 0; c < 4; c++)
            #pragma unroll
            for (int p = 0; p < 4; p++)
                FMA_F32X2(accp[c][p], xp[p], ws[c], accp[c][p]);
    }

    float4 bv = *(const float4*)(b2s + cg * 4);
    #pragma unroll
    for (int p = 0; p < 4; p++) {
        float2 f0 = *(float2*)&accp[0][p];
        float2 f1 = *(float2*)&accp[1][p];
        float2 f2 = *(float2*)&accp[2][p];
        float2 f3 = *(float2*)&accp[3][p];
        int rowe = row0 + rg * 8 + 2 * p;
        if (rowe < N) {
            __half2 h01 = __floats2half2_rn(f0.x + bv.x, f1.x + bv.y);
            __half2 h23 = __floats2half2_rn(f2.x + bv.z, f3.x + bv.w);
            uint2 st = make_uint2(*(unsigned*)&h01, *(unsigned*)&h23);
            *(uint2*)(prevbuf + (size_t)rowe * 64 + cg * 4) = st;
        }
        int rowo = rowe + 1;
        if (rowo < N) {
            __half2 h01 = __floats2half2_rn(f0.y + bv.x, f1.y + bv.y);
            __half2 h23 = __floats2half2_rn(f2.y + bv.z, f3.y + bv.w);
            uint2 st = make_uint2(*(unsigned*)&h01, *(unsigned*)&h23);
            *(uint2*)(prevbuf + (size_t)rowo * 64 + cg * 4) = st;
        }
    }
}

// ---------------------------------------------------------------------------
// CSR SpMM (fp16 gather, fp32 accumulate). 8 lanes/row, 8 dims/lane.
// mode 0 (layer 0): next = acc;  sum (=/+=) h(prev[row]) + acc
// mode 1 (layer 1): next = acc
// mode 2 (layer 2): sum += p2(prev[row]) + (mask ? acc : p2)
// ---------------------------------------------------------------------------
__global__ void __launch_bounds__(256) spmm_half_kernel(
    const int* __restrict__ start, const int2* __restrict__ edges,
    const __half* __restrict__ prev, __half* __restrict__ next,
    float* __restrict__ sum, int rbase, int N,
    int mode, unsigned long long mask, int first)
{
    int row  = blockIdx.x * 32 + (threadIdx.x >> 3);
    int lane = threadIdx.x & 7;
    if (row >= N) return;

    int s = __ldg(start + rbase + row);
    int e = __ldg(start + rbase + row + 1);

    float acc[8];
    #pragma unroll
    for (int d = 0; d < 8; d++) acc[d] = 0.f;

    int j = s;
    for (; j + 1 < e; j += 2) {
        int2 e0 = __ldg(edges + j);
        int2 e1 = __ldg(edges + j + 1);
        float4 r0 = __ldg((const float4*)(prev + (size_t)e0.x * 64) + lane);
        float4 r1 = __ldg((const float4*)(prev + (size_t)e1.x * 64) + lane);
        float v0 = __int_as_float(e0.y);
        float v1 = __int_as_float(e1.y);
        const __half2* h0 = (const __half2*)&r0;
        const __half2* h1 = (const __half2*)&r1;
        #pragma unroll
        for (int q = 0; q < 4; q++) {
            float2 f0 = __half22float2(h0[q]);
            float2 f1 = __half22float2(h1[q]);
            acc[2 * q]     += v0 * f0.x + v1 * f1.x;
            acc[2 * q + 1] += v0 * f0.y + v1 * f1.y;
        }
    }
    if (j < e) {
        int2 e0 = __ldg(edges + j);
        float4 r0 = __ldg((const float4*)(prev + (size_t)e0.x * 64) + lane);
        float v0 = __int_as_float(e0.y);
        const __half2* h0 = (const __half2*)&r0;
        #pragma unroll
        for (int q = 0; q < 4; q++) {
            float2 f0 = __half22float2(h0[q]);
            acc[2 * q]     += v0 * f0.x;
            acc[2 * q + 1] += v0 * f0.y;
        }
    }

    const size_t off = (size_t)row * 64 + lane * 8;

    if (mode == 0) {
        // next = acc
        __half2 o0 = __floats2half2_rn(acc[0], acc[1]);
        __half2 o1 = __floats2half2_rn(acc[2], acc[3]);
        __half2 o2 = __floats2half2_rn(acc[4], acc[5]);
        __half2 o3 = __floats2half2_rn(acc[6], acc[7]);
        uint4 st = make_uint4(*(unsigned*)&o0, *(unsigned*)&o1,
                              *(unsigned*)&o2, *(unsigned*)&o3);
        *(uint4*)(next + off) = st;
        // sum = / += h + acc
        float4 hraw = __ldg((const float4*)(prev + off));
        const __half2* hh = (const __half2*)&hraw;
        float hv[8];
        #pragma unroll
        for (int q = 0; q < 4; q++) {
            float2 f = __half22float2(hh[q]);
            hv[2 * q] = f.x; hv[2 * q + 1] = f.y;
        }
        float* sp = sum + off;
        if (first) {
            float4 s0 = make_float4(hv[0] + acc[0], hv[1] + acc[1],
                                    hv[2] + acc[2], hv[3] + acc[3]);
            float4 s1 = make_float4(hv[4] + acc[4], hv[5] + acc[5],
                                    hv[6] + acc[6], hv[7] + acc[7]);
            *(float4*)sp = s0;
            *(float4*)(sp + 4) = s1;
        } else {
            float4 s0 = *(float4*)sp;
            float4 s1 = *(float4*)(sp + 4);
            s0.x += hv[0] + acc[0]; s0.y += hv[1] + acc[1];
            s0.z += hv[2] + acc[2]; s0.w += hv[3] + acc[3];
            s1.x += hv[4] + acc[4]; s1.y += hv[5] + acc[5];
            s1.z += hv[6] + acc[6]; s1.w += hv[7] + acc[7];
            *(float4*)sp = s0;
            *(float4*)(sp + 4) = s1;
        }
    } else if (mode == 1) {
        __half2 o0 = __floats2half2_rn(acc[0], acc[1]);
        __half2 o1 = __floats2half2_rn(acc[2], acc[3]);
        __half2 o2 = __floats2half2_rn(acc[4], acc[5]);
        __half2 o3 = __floats2half2_rn(acc[6], acc[7]);
        uint4 st = make_uint4(*(unsigned*)&o0, *(unsigned*)&o1,
                              *(unsigned*)&o2, *(unsigned*)&o3);
        *(uint4*)(next + off) = st;
    } else {
        // sum += p2 + (mask ? acc : p2)
        float4 praw = __ldg((const float4*)(prev + off));
        const __half2* ph = (const __half2*)&praw;
        float pv[8];
        #pragma unroll
        for (int q = 0; q < 4; q++) {
            float2 f = __half22float2(ph[q]);
            pv[2 * q] = f.x; pv[2 * q + 1] = f.y;
        }
        unsigned mb = (unsigned)((mask >> (lane * 8)) & 0xFFull);
        float contrib[8];
        #pragma unroll
        for (int d = 0; d < 8; d++)
            contrib[d] = pv[d] + (((mb >> d) & 1u) ? acc[d] : pv[d]);
        float* sp = sum + off;
        float4 s0 = *(float4*)sp;
        float4 s1 = *(float4*)(sp + 4);
        s0.x += contrib[0]; s0.y += contrib[1];
        s0.z += contrib[2]; s0.w += contrib[3];
        s1.x += contrib[4]; s1.y += contrib[5];
        s1.z += contrib[6]; s1.w += contrib[7];
        *(float4*)sp = s0;
        *(float4*)(sp + 4) = s1;
    }
}

// ---------------------------------------------------------------------------
// Final: out[b] = (sum[u] . sum[U+i]) / R^2
// ---------------------------------------------------------------------------
__global__ void final_kernel(const int* __restrict__ users,
                             const int* __restrict__ items,
                             const float* __restrict__ sum,
                             int U, float invR2,
                             float* __restrict__ out, int B)
{
    int b = blockIdx.x * (blockDim.x >> 5) + (threadIdx.x >> 5);
    int lane = threadIdx.x & 31;
    if (b >= B) return;
    int u = users[b];
    int it = items[b];
    const float* pu = sum + (size_t)u * 64;
    const float* pi = sum + ((size_t)U + it) * 64;
    float acc = pu[lane] * pi[lane] + pu[lane + 32] * pi[lane + 32];
    #pragma unroll
    for (int off = 16; off; off >>= 1)
        acc += __shfl_xor_sync(0xffffffffu, acc, off);
    if (lane == 0) out[b] = acc * invR2;
}

// ---------------------------------------------------------------------------
// Host: numpy MT19937 RandomState(2).permutation(64) -> layer-2 mask bits
// ---------------------------------------------------------------------------
static unsigned long long compute_layer2_mask(int d)
{
    const int NN = 624, MM = 397;
    unsigned int key[624];
    unsigned int s = 2u;
    for (int i = 0; i < NN; i++) {
        key[i] = s;
        s = 1812433253u * (s ^ (s >> 30)) + (unsigned)i + 1u;
    }
    int pos = NN;
    auto next_u32 = [&]() -> unsigned int {
        if (pos == NN) {
            for (int i = 0; i < NN; i++) {
                unsigned int y = (key[i] & 0x80000000u) |
                                 (key[(i + 1) % NN] & 0x7fffffffu);
                unsigned int v = key[(i + MM) % NN] ^ (y >> 1);
                if (y & 1u) v ^= 0x9908b0dfu;
                key[i] = v;
            }
            pos = 0;
        }
        unsigned int y = key[pos++];
        y ^= y >> 11;
        y ^= (y << 7)  & 0x9d2c5680u;
        y ^= (y << 15) & 0xefc60000u;
        y ^= y >> 18;
        return y;
    };
    int perm[64];
    for (int i = 0; i < d; i++) perm[i] = i;
    for (int i = d - 1; i > 0; i--) {
        unsigned int m = (unsigned)i;
        m |= m >> 1; m |= m >> 2; m |= m >> 4; m |= m >> 8; m |= m >> 16;
        unsigned int j;
        do { j = next_u32() & m; } while (j > (unsigned)i);
        int t = perm[i]; perm[i] = perm[j]; perm[j] = t;
    }
    double ratio = 1.0 - log(1.0 / 2.0 + 1.0);
    int nm = (int)(ratio * d);
    unsigned long long bits = 0ull;
    for (int i = 0; i < d; i++)
        if (perm[i] >= nm) bits |= (1ull << i);
    return bits;
}

// ---------------------------------------------------------------------------
extern "C" void kernel_launch(void* const* d_in, const int* in_sizes, int n_in,
                              void* d_out, int out_size)
{
    const int*   users      = (const int*)  d_in[0];
    const int*   items      = (const int*)  d_in[1];
    const float* user_emb   = (const float*)d_in[2];
    const float* item_emb   = (const float*)d_in[3];
    const float* rating_emb = (const float*)d_in[4];
    const float* W1         = (const float*)d_in[5];
    const float* b1         = (const float*)d_in[6];
    const float* W2         = (const float*)d_in[7];
    const float* b2         = (const float*)d_in[8];
    const int*   rows       = (const int*)  d_in[9];
    const int*   cols       = (const int*)  d_in[10];
    const float* vals       = (const float*)d_in[11];

    const int B = in_sizes[0];
    const int U = in_sizes[2] / D;
    const int I = in_sizes[3] / D;
    const int N = U + I;
    const int R = in_sizes[4] / D;
    const int E = in_sizes[9] / R;

    __half *bufA, *bufB;
    float *sumb;
    int *deg, *startp, *bsum;
    int2 *edges;
    cudaGetSymbolAddress((void**)&bufA,  g_bufA);
    cudaGetSymbolAddress((void**)&bufB,  g_bufB);
    cudaGetSymbolAddress((void**)&sumb,  g_sum);
    cudaGetSymbolAddress((void**)&deg,   g_deg);
    cudaGetSymbolAddress((void**)&startp,g_start);
    cudaGetSymbolAddress((void**)&bsum,  g_bsum);
    cudaGetSymbolAddress((void**)&edges, g_edges);

    const unsigned long long mask2 = compute_layer2_mask(D);

    // ---- CSR build ----
    const int totRN = R * N;
    const int totRE = R * E;
    const int nblk  = (totRN + 1023) / 1024;

    zero_deg_kernel<<<(totRN + 255) / 256, 256>>>(deg, totRN);
    hist_kernel<<<(totRE + 255) / 256, 256>>>(rows, E, N, deg, totRE);
    scanA_kernel<<<nblk, 1024>>>(deg, totRN, startp, bsum);
    scanB_kernel<<<1, 1024>>>(bsum, nblk);
    scanC_kernel<<<nblk, 1024>>>(startp, deg, bsum, totRN, totRE);
    scatter_kernel<<<(totRE + 255) / 256, 256>>>(rows, cols, vals, E, N,
                                                 deg, edges, totRE);

    // ---- per-rating pipeline ----
    const int smem_bytes = (64 * 132 + 64 * 64 + 64 * 64 + 64 + 64) * 4;
    cudaFuncSetAttribute(mlp_kernel, cudaFuncAttributeMaxDynamicSharedMemorySize,
                         smem_bytes);
    const int mlp_grid  = (N + MLP_ROWS - 1) / MLP_ROWS;
    const int spmm_grid = (N + 31) / 32;

    for (int r = 0; r < R; r++) {
        mlp_kernel<<<mlp_grid, MLP_THREADS, smem_bytes>>>(
            user_emb, item_emb, U, N, W1, b1, W2, b2, rating_emb, r, bufA);

        int rbase = r * N;
        // layer 0: A -> B, sum (=/+=) h + p1
        spmm_half_kernel<<<spmm_grid, 256>>>(startp, edges, bufA, bufB, sumb,
                                             rbase, N, 0, 0ull, (r == 0) ? 1 : 0);
        // layer 1: B -> A (p2)
        spmm_half_kernel<<<spmm_grid, 256>>>(startp, edges, bufB, bufA, sumb,
                                             rbase, N, 1, 0ull, 0);
        // layer 2: A -> sum += p2 + (mask ? A*p2 : p2)
        spmm_half_kernel<<<spmm_grid, 256>>>(startp, edges, bufA, bufB, sumb,
                                             rbase, N, 2, mask2, 0);
    }

    const float invR2 = 1.0f / (float)(R * R);
    const int fin_grid = (B + 7) / 8;
    final_kernel<<<fin_grid, 256>>>(users, items, sumb, U, invR2,
                                    (float*)d_out, B);
}

// round 4
// speedup vs baseline: 1.9805x; 1.0496x over previous
#include <cuda_runtime.h>
#include <cuda_fp16.h>
#include <math.h>
#include <stdint.h>

// ---------------------------------------------------------------------------
// DCGCN: U=I=50000 (N=100000), R=5, D=64, E=1e6/rating, B=8192. Output f32[B].
// R4: all-ratings-batched stages (3 SpMM launches total), red.add sum
//     epilogues, per-rating fp16 ping-pong buffers.
// ---------------------------------------------------------------------------

#define D 64
#define MAXN 100352
#define MAXR 5
#define MAXE 1048576
#define MLP_ROWS 128
#define MLP_THREADS 256

__device__ __half g_bufA[(size_t)MAXR * MAXN * D];
__device__ __half g_bufB[(size_t)MAXR * MAXN * D];
__device__ float  g_sum [(size_t)MAXN * D];
__device__ int    g_deg  [MAXR * MAXN];
__device__ int    g_start[MAXR * MAXN + 1];
__device__ int    g_bsum [2048];
__device__ int2   g_edges[(size_t)MAXR * MAXE];

#define FMA_F32X2(d, a, b, c) \
    asm("fma.rn.f32x2 %0, %1, %2, %3;" : "=l"(d) : "l"(a), "l"(b), "l"(c))
#define SPLAT_F32X2(out, f) \
    asm("mov.b64 %0, {%1, %1};" : "=l"(out) : "r"(__float_as_uint(f)))

__device__ __forceinline__ void red_add_v4(float* addr, float4 v) {
    asm volatile("red.global.add.v4.f32 [%0], {%1,%2,%3,%4};"
                 :: "l"(addr), "f"(v.x), "f"(v.y), "f"(v.z), "f"(v.w)
                 : "memory");
}

// ---------------------------------------------------------------------------
// CSR build
// ---------------------------------------------------------------------------
__global__ void zero_deg_kernel(int* __restrict__ deg, int tot)
{
    int i = blockIdx.x * blockDim.x + threadIdx.x;
    if (i < tot) deg[i] = 0;
}

__global__ void hist_kernel(const int* __restrict__ rows, int E, int N,
                            int* __restrict__ deg, int tot)
{
    int i = blockIdx.x * blockDim.x + threadIdx.x;
    if (i >= tot) return;
    int r = i / E;
    atomicAdd(&deg[r * N + rows[i]], 1);
}

__global__ void __launch_bounds__(1024) scanA_kernel(
    const int* __restrict__ deg, int tot,
    int* __restrict__ out, int* __restrict__ bsum)
{
    __shared__ int sm[1024];
    int i = blockIdx.x * 1024 + threadIdx.x;
    int v = (i < tot) ? deg[i] : 0;
    sm[threadIdx.x] = v;
    __syncthreads();
    #pragma unroll
    for (int o = 1; o < 1024; o <<= 1) {
        int t = (threadIdx.x >= o) ? sm[threadIdx.x - o] : 0;
        __syncthreads();
        sm[threadIdx.x] += t;
        __syncthreads();
    }
    if (i < tot) out[i] = sm[threadIdx.x] - v;
    if (threadIdx.x == 1023) bsum[blockIdx.x] = sm[1023];
}

__global__ void __launch_bounds__(1024) scanB_kernel(int* __restrict__ bsum, int nblk)
{
    __shared__ int sm[2048];
    for (int i = threadIdx.x; i < 2048; i += 1024)
        sm[i] = (i < nblk) ? bsum[i] : 0;
    __syncthreads();
    for (int o = 1; o < 2048; o <<= 1) {
        int t0 = (threadIdx.x >= o) ? sm[threadIdx.x - o] : 0;
        int i1 = threadIdx.x + 1024;
        int t1 = (i1 >= o) ? sm[i1 - o] : 0;
        __syncthreads();
        sm[threadIdx.x] += t0;
        sm[i1] += t1;
        __syncthreads();
    }
    int v0 = (threadIdx.x < nblk) ? ((threadIdx.x == 0) ? 0 : sm[threadIdx.x - 1]) : 0;
    int i1 = threadIdx.x + 1024;
    int v1 = (i1 < nblk) ? sm[i1 - 1] : 0;
    __syncthreads();
    if (threadIdx.x < nblk) bsum[threadIdx.x] = v0;
    if (i1 < nblk) bsum[i1] = v1;
}

__global__ void __launch_bounds__(1024) scanC_kernel(
    int* __restrict__ start, int* __restrict__ cursor,
    const int* __restrict__ bsum, int tot, int totE)
{
    int i = blockIdx.x * 1024 + threadIdx.x;
    if (i < tot) {
        int v = start[i] + bsum[blockIdx.x];
        start[i]  = v;
        cursor[i] = v;
    }
    if (i == 0) start[tot] = totE;
}

__global__ void scatter_kernel(const int* __restrict__ rows,
                               const int* __restrict__ cols,
                               const float* __restrict__ vals,
                               int E, int N, int* __restrict__ cursor,
                               int2* __restrict__ edges, int tot)
{
    int i = blockIdx.x * blockDim.x + threadIdx.x;
    if (i >= tot) return;
    int r = i / E;
    int pos = atomicAdd(&cursor[r * N + rows[i]], 1);
    edges[pos] = make_int2(cols[i], __float_as_int(vals[i]));
}

__global__ void zero_sum_kernel(float4* __restrict__ sum, int n4)
{
    int i = blockIdx.x * blockDim.x + threadIdx.x;
    if (i < n4) sum[i] = make_float4(0.f, 0.f, 0.f, 0.f);
}

// ---------------------------------------------------------------------------
// MLP (all ratings, blockIdx.y = r):
//   h = leaky_relu(base @ W1a + c1) @ W2 + b2 ; out(half, rating-strided) = h
// ---------------------------------------------------------------------------
__global__ void __launch_bounds__(MLP_THREADS) mlp_kernel(
    const float* __restrict__ user_emb, const float* __restrict__ item_emb,
    int U, int N,
    const float* __restrict__ W1, const float* __restrict__ b1,
    const float* __restrict__ W2, const float* __restrict__ b2,
    const float* __restrict__ rating_emb,
    __half* __restrict__ outbuf)
{
    extern __shared__ float smem[];
    float* xs  = smem;                   // 64*132
    float* W1s = xs + 64 * 132;
    float* W2s = W1s + 64 * 64;
    float* c1s = W2s + 64 * 64;
    float* b2s = c1s + 64;

    const int r = blockIdx.y;
    const float* W1r = W1 + (size_t)r * 128 * 64;
    const float* W2r = W2 + (size_t)r * 64 * 64;
    __half* prevbuf = outbuf + (size_t)r * MAXN * D;
    const int tid = threadIdx.x;
    const int row0 = blockIdx.x * MLP_ROWS;

    for (int i = tid; i < 1024; i += MLP_THREADS) {
        ((float4*)W1s)[i] = ((const float4*)W1r)[i];
        ((float4*)W2s)[i] = ((const float4*)W2r)[i];
    }
    if (tid < 64) {
        float c = b1[r * 64 + tid];
        #pragma unroll 8
        for (int k = 0; k < 64; k++)
            c += rating_emb[r * 64 + k] * W1r[(64 + k) * 64 + tid];
        c1s[tid] = c;
        b2s[tid] = b2[r * 64 + tid];
    }
    for (int i = tid; i < MLP_ROWS * 16; i += MLP_THREADS) {
        int rr = i >> 4;
        int c4 = i & 15;
        int row = row0 + rr;
        float4 v = make_float4(0.f, 0.f, 0.f, 0.f);
        if (row < N) {
            const float* src = (row < U) ? (user_emb + (size_t)row * 64)
                                         : (item_emb + (size_t)(row - U) * 64);
            v = ((const float4*)src)[c4];
        }
        xs[(4 * c4 + 0) * 132 + rr] = v.x;
        xs[(4 * c4 + 1) * 132 + rr] = v.y;
        xs[(4 * c4 + 2) * 132 + rr] = v.z;
        xs[(4 * c4 + 3) * 132 + rr] = v.w;
    }
    __syncthreads();

    const int rg = tid >> 4;
    const int cg = tid & 15;

    unsigned long long accp[4][4];

    #pragma unroll
    for (int c = 0; c < 4; c++)
        #pragma unroll
        for (int p = 0; p < 4; p++) accp[c][p] = 0ull;

    #pragma unroll 4
    for (int k = 0; k < 64; k++) {
        float4 x0 = *(const float4*)(xs + k * 132 + rg * 8);
        float4 x1 = *(const float4*)(xs + k * 132 + rg * 8 + 4);
        float4 w  = *(const float4*)(W1s + k * 64 + cg * 4);
        unsigned long long xp[4];
        xp[0] = ((const unsigned long long*)&x0)[0];
        xp[1] = ((const unsigned long long*)&x0)[1];
        xp[2] = ((const unsigned long long*)&x1)[0];
        xp[3] = ((const unsigned long long*)&x1)[1];
        unsigned long long ws[4];
        SPLAT_F32X2(ws[0], w.x);
        SPLAT_F32X2(ws[1], w.y);
        SPLAT_F32X2(ws[2], w.z);
        SPLAT_F32X2(ws[3], w.w);
        #pragma unroll
        for (int c = 0; c < 4; c++)
            #pragma unroll
            for (int p = 0; p < 4; p++)
                FMA_F32X2(accp[c][p], xp[p], ws[c], accp[c][p]);
    }
    __syncthreads();

    #pragma unroll
    for (int c = 0; c < 4; c++) {
        float cc = c1s[cg * 4 + c];
        #pragma unroll
        for (int p = 0; p < 4; p++) {
            float2 f = *(float2*)&accp[c][p];
            float v0 = f.x + cc; v0 = (v0 > 0.f) ? v0 : 0.01f * v0;
            float v1 = f.y + cc; v1 = (v1 > 0.f) ? v1 : 0.01f * v1;
            xs[(cg * 4 + c) * 132 + rg * 8 + 2 * p]     = v0;
            xs[(cg * 4 + c) * 132 + rg * 8 + 2 * p + 1] = v1;
        }
    }
    __syncthreads();

    #pragma unroll
    for (int c = 0; c < 4; c++)
        #pragma unroll
        for (int p = 0; p < 4; p++) accp[c][p] = 0ull;

    #pragma unroll 4
    for (int k = 0; k < 64; k++) {
        float4 x0 = *(const float4*)(xs + k * 132 + rg * 8);
        float4 x1 = *(const float4*)(xs + k * 132 + rg * 8 + 4);
        float4 w  = *(const float4*)(W2s + k * 64 + cg * 4);
        unsigned long long xp[4];
        xp[0] = ((const unsigned long long*)&x0)[0];
        xp[1] = ((const unsigned long long*)&x0)[1];
        xp[2] = ((const unsigned long long*)&x1)[0];
        xp[3] = ((const unsigned long long*)&x1)[1];
        unsigned long long ws[4];
        SPLAT_F32X2(ws[0], w.x);
        SPLAT_F32X2(ws[1], w.y);
        SPLAT_F32X2(ws[2], w.z);
        SPLAT_F32X2(ws[3], w.w);
        #pragma unroll
        for (int c = 0; c < 4; c++)
            #pragma unroll
            for (int p = 0; p < 4; p++)
                FMA_F32X2(accp[c][p], xp[p], ws[c], accp[c][p]);
    }

    float4 bv = *(const float4*)(b2s + cg * 4);
    #pragma unroll
    for (int p = 0; p < 4; p++) {
        float2 f0 = *(float2*)&accp[0][p];
        float2 f1 = *(float2*)&accp[1][p];
        float2 f2 = *(float2*)&accp[2][p];
        float2 f3 = *(float2*)&accp[3][p];
        int rowe = row0 + rg * 8 + 2 * p;
        if (rowe < N) {
            __half2 h01 = __floats2half2_rn(f0.x + bv.x, f1.x + bv.y);
            __half2 h23 = __floats2half2_rn(f2.x + bv.z, f3.x + bv.w);
            uint2 st = make_uint2(*(unsigned*)&h01, *(unsigned*)&h23);
            *(uint2*)(prevbuf + (size_t)rowe * 64 + cg * 4) = st;
        }
        int rowo = rowe + 1;
        if (rowo < N) {
            __half2 h01 = __floats2half2_rn(f0.y + bv.x, f1.y + bv.y);
            __half2 h23 = __floats2half2_rn(f2.y + bv.z, f3.y + bv.w);
            uint2 st = make_uint2(*(unsigned*)&h01, *(unsigned*)&h23);
            *(uint2*)(prevbuf + (size_t)rowo * 64 + cg * 4) = st;
        }
    }
}

// ---------------------------------------------------------------------------
// CSR SpMM over ALL ratings (fp16 gather, fp32 accumulate).
// Global row gr in [0, R*N). 8 lanes/row, 8 dims/lane.
// mode 0 (layer 0): next = acc; red.add(sum, h + acc)      (sum pre-zeroed)
// mode 1 (layer 1): next = acc
// mode 2 (layer 2): red.add(sum, p2 + (mask ? acc : p2))
// ---------------------------------------------------------------------------
__global__ void __launch_bounds__(256) spmm_all_kernel(
    const int* __restrict__ start, const int2* __restrict__ edges,
    const __half* __restrict__ prevbase, __half* __restrict__ nextbase,
    float* __restrict__ sum, int N, int RN,
    int mode, unsigned long long mask)
{
    int gr   = blockIdx.x * 32 + (threadIdx.x >> 3);
    int lane = threadIdx.x & 7;
    if (gr >= RN) return;
    int r   = gr / N;
    int row = gr - r * N;

    const __half* prev_r = prevbase + (size_t)r * MAXN * D;

    int s = __ldg(start + gr);
    int e = __ldg(start + gr + 1);

    float acc[8];
    #pragma unroll
    for (int d = 0; d < 8; d++) acc[d] = 0.f;

    int j = s;
    for (; j + 1 < e; j += 2) {
        int2 e0 = __ldg(edges + j);
        int2 e1 = __ldg(edges + j + 1);
        float4 r0 = __ldg((const float4*)(prev_r + (size_t)e0.x * 64) + lane);
        float4 r1 = __ldg((const float4*)(prev_r + (size_t)e1.x * 64) + lane);
        float v0 = __int_as_float(e0.y);
        float v1 = __int_as_float(e1.y);
        const __half2* h0 = (const __half2*)&r0;
        const __half2* h1 = (const __half2*)&r1;
        #pragma unroll
        for (int q = 0; q < 4; q++) {
            float2 f0 = __half22float2(h0[q]);
            float2 f1 = __half22float2(h1[q]);
            acc[2 * q]     += v0 * f0.x + v1 * f1.x;
            acc[2 * q + 1] += v0 * f0.y + v1 * f1.y;
        }
    }
    if (j < e) {
        int2 e0 = __ldg(edges + j);
        float4 r0 = __ldg((const float4*)(prev_r + (size_t)e0.x * 64) + lane);
        float v0 = __int_as_float(e0.y);
        const __half2* h0 = (const __half2*)&r0;
        #pragma unroll
        for (int q = 0; q < 4; q++) {
            float2 f0 = __half22float2(h0[q]);
            acc[2 * q]     += v0 * f0.x;
            acc[2 * q + 1] += v0 * f0.y;
        }
    }

    const size_t goff = (size_t)r * MAXN * D + (size_t)row * 64 + lane * 8;
    const size_t soff = (size_t)row * 64 + lane * 8;

    if (mode == 0) {
        __half2 o0 = __floats2half2_rn(acc[0], acc[1]);
        __half2 o1 = __floats2half2_rn(acc[2], acc[3]);
        __half2 o2 = __floats2half2_rn(acc[4], acc[5]);
        __half2 o3 = __floats2half2_rn(acc[6], acc[7]);
        uint4 st = make_uint4(*(unsigned*)&o0, *(unsigned*)&o1,
                              *(unsigned*)&o2, *(unsigned*)&o3);
        *(uint4*)(nextbase + goff) = st;
        float4 hraw = __ldg((const float4*)(prevbase + goff));
        const __half2* hh = (const __half2*)&hraw;
        float hv[8];
        #pragma unroll
        for (int q = 0; q < 4; q++) {
            float2 f = __half22float2(hh[q]);
            hv[2 * q] = f.x; hv[2 * q + 1] = f.y;
        }
        red_add_v4(sum + soff, make_float4(hv[0] + acc[0], hv[1] + acc[1],
                                           hv[2] + acc[2], hv[3] + acc[3]));
        red_add_v4(sum + soff + 4, make_float4(hv[4] + acc[4], hv[5] + acc[5],
                                               hv[6] + acc[6], hv[7] + acc[7]));
    } else if (mode == 1) {
        __half2 o0 = __floats2half2_rn(acc[0], acc[1]);
        __half2 o1 = __floats2half2_rn(acc[2], acc[3]);
        __half2 o2 = __floats2half2_rn(acc[4], acc[5]);
        __half2 o3 = __floats2half2_rn(acc[6], acc[7]);
        uint4 st = make_uint4(*(unsigned*)&o0, *(unsigned*)&o1,
                              *(unsigned*)&o2, *(unsigned*)&o3);
        *(uint4*)(nextbase + goff) = st;
    } else {
        float4 praw = __ldg((const float4*)(prevbase + goff));
        const __half2* ph = (const __half2*)&praw;
        float pv[8];
        #pragma unroll
        for (int q = 0; q < 4; q++) {
            float2 f = __half22float2(ph[q]);
            pv[2 * q] = f.x; pv[2 * q + 1] = f.y;
        }
        unsigned mb = (unsigned)((mask >> (lane * 8)) & 0xFFull);
        float contrib[8];
        #pragma unroll
        for (int d = 0; d < 8; d++)
            contrib[d] = pv[d] + (((mb >> d) & 1u) ? acc[d] : pv[d]);
        red_add_v4(sum + soff, make_float4(contrib[0], contrib[1],
                                           contrib[2], contrib[3]));
        red_add_v4(sum + soff + 4, make_float4(contrib[4], contrib[5],
                                               contrib[6], contrib[7]));
    }
}

// ---------------------------------------------------------------------------
// Final: out[b] = (sum[u] . sum[U+i]) / R^2
// ---------------------------------------------------------------------------
__global__ void final_kernel(const int* __restrict__ users,
                             const int* __restrict__ items,
                             const float* __restrict__ sum,
                             int U, float invR2,
                             float* __restrict__ out, int B)
{
    int b = blockIdx.x * (blockDim.x >> 5) + (threadIdx.x >> 5);
    int lane = threadIdx.x & 31;
    if (b >= B) return;
    int u = users[b];
    int it = items[b];
    const float* pu = sum + (size_t)u * 64;
    const float* pi = sum + ((size_t)U + it) * 64;
    float acc = pu[lane] * pi[lane] + pu[lane + 32] * pi[lane + 32];
    #pragma unroll
    for (int off = 16; off; off >>= 1)
        acc += __shfl_xor_sync(0xffffffffu, acc, off);
    if (lane == 0) out[b] = acc * invR2;
}

// ---------------------------------------------------------------------------
// Host: numpy MT19937 RandomState(2).permutation(64) -> layer-2 mask bits
// ---------------------------------------------------------------------------
static unsigned long long compute_layer2_mask(int d)
{
    const int NN = 624, MM = 397;
    unsigned int key[624];
    unsigned int s = 2u;
    for (int i = 0; i < NN; i++) {
        key[i] = s;
        s = 1812433253u * (s ^ (s >> 30)) + (unsigned)i + 1u;
    }
    int pos = NN;
    auto next_u32 = [&]() -> unsigned int {
        if (pos == NN) {
            for (int i = 0; i < NN; i++) {
                unsigned int y = (key[i] & 0x80000000u) |
                                 (key[(i + 1) % NN] & 0x7fffffffu);
                unsigned int v = key[(i + MM) % NN] ^ (y >> 1);
                if (y & 1u) v ^= 0x9908b0dfu;
                key[i] = v;
            }
            pos = 0;
        }
        unsigned int y = key[pos++];
        y ^= y >> 11;
        y ^= (y << 7)  & 0x9d2c5680u;
        y ^= (y << 15) & 0xefc60000u;
        y ^= y >> 18;
        return y;
    };
    int perm[64];
    for (int i = 0; i < d; i++) perm[i] = i;
    for (int i = d - 1; i > 0; i--) {
        unsigned int m = (unsigned)i;
        m |= m >> 1; m |= m >> 2; m |= m >> 4; m |= m >> 8; m |= m >> 16;
        unsigned int j;
        do { j = next_u32() & m; } while (j > (unsigned)i);
        int t = perm[i]; perm[i] = perm[j]; perm[j] = t;
    }
    double ratio = 1.0 - log(1.0 / 2.0 + 1.0);
    int nm = (int)(ratio * d);
    unsigned long long bits = 0ull;
    for (int i = 0; i < d; i++)
        if (perm[i] >= nm) bits |= (1ull << i);
    return bits;
}

// ---------------------------------------------------------------------------
extern "C" void kernel_launch(void* const* d_in, const int* in_sizes, int n_in,
                              void* d_out, int out_size)
{
    const int*   users      = (const int*)  d_in[0];
    const int*   items      = (const int*)  d_in[1];
    const float* user_emb   = (const float*)d_in[2];
    const float* item_emb   = (const float*)d_in[3];
    const float* rating_emb = (const float*)d_in[4];
    const float* W1         = (const float*)d_in[5];
    const float* b1         = (const float*)d_in[6];
    const float* W2         = (const float*)d_in[7];
    const float* b2         = (const float*)d_in[8];
    const int*   rows       = (const int*)  d_in[9];
    const int*   cols       = (const int*)  d_in[10];
    const float* vals       = (const float*)d_in[11];

    const int B = in_sizes[0];
    const int U = in_sizes[2] / D;
    const int I = in_sizes[3] / D;
    const int N = U + I;
    const int R = in_sizes[4] / D;
    const int E = in_sizes[9] / R;

    __half *bufA, *bufB;
    float *sumb;
    int *deg, *startp, *bsum;
    int2 *edges;
    cudaGetSymbolAddress((void**)&bufA,  g_bufA);
    cudaGetSymbolAddress((void**)&bufB,  g_bufB);
    cudaGetSymbolAddress((void**)&sumb,  g_sum);
    cudaGetSymbolAddress((void**)&deg,   g_deg);
    cudaGetSymbolAddress((void**)&startp,g_start);
    cudaGetSymbolAddress((void**)&bsum,  g_bsum);
    cudaGetSymbolAddress((void**)&edges, g_edges);

    const unsigned long long mask2 = compute_layer2_mask(D);

    // ---- CSR build (all ratings) ----
    const int totRN = R * N;
    const int totRE = R * E;
    const int nblk  = (totRN + 1023) / 1024;

    zero_deg_kernel<<<(totRN + 255) / 256, 256>>>(deg, totRN);
    hist_kernel<<<(totRE + 255) / 256, 256>>>(rows, E, N, deg, totRE);
    scanA_kernel<<<nblk, 1024>>>(deg, totRN, startp, bsum);
    scanB_kernel<<<1, 1024>>>(bsum, nblk);
    scanC_kernel<<<nblk, 1024>>>(startp, deg, bsum, totRN, totRE);
    scatter_kernel<<<(totRE + 255) / 256, 256>>>(rows, cols, vals, E, N,
                                                 deg, edges, totRE);

    // ---- zero sum ----
    const int n4 = N * (D / 4);
    zero_sum_kernel<<<(n4 + 255) / 256, 256>>>((float4*)sumb, n4);

    // ---- MLP for all ratings (one launch) ----
    const int smem_bytes = (64 * 132 + 64 * 64 + 64 * 64 + 64 + 64) * 4;
    cudaFuncSetAttribute(mlp_kernel, cudaFuncAttributeMaxDynamicSharedMemorySize,
                         smem_bytes);
    dim3 mlp_grid((N + MLP_ROWS - 1) / MLP_ROWS, R);
    mlp_kernel<<<mlp_grid, MLP_THREADS, smem_bytes>>>(
        user_emb, item_emb, U, N, W1, b1, W2, b2, rating_emb, bufA);

    // ---- 3 SpMM layers, each covering all ratings ----
    const int spmm_grid = (totRN + 31) / 32;
    // layer 0: A -> B, sum += h + p1
    spmm_all_kernel<<<spmm_grid, 256>>>(startp, edges, bufA, bufB, sumb,
                                        N, totRN, 0, 0ull);
    // layer 1: B -> A
    spmm_all_kernel<<<spmm_grid, 256>>>(startp, edges, bufB, bufA, sumb,
                                        N, totRN, 1, 0ull);
    // layer 2: A -> sum += p2 + (mask ? A*p2 : p2)
    spmm_all_kernel<<<spmm_grid, 256>>>(startp, edges, bufA, bufB, sumb,
                                        N, totRN, 2, mask2);

    const float invR2 = 1.0f / (float)(R * R);
    const int fin_grid = (B + 7) / 8;
    final_kernel<<<fin_grid, 256>>>(users, items, sumb, U, invR2,
                                    (float*)d_out, B);
}

// round 5
// speedup vs baseline: 2.3975x; 1.2105x over previous
#include <cuda_runtime.h>
#include <cuda_fp16.h>
#include <math.h>
#include <stdint.h>

// ---------------------------------------------------------------------------
// DCGCN: U=I=50000 (N=100000), R=5, D=64, E=1e6/rating, B=8192. Output f32[B].
// R5: HMMA (mma.sync m16n8k16 fp16->fp32) MLP, batched stages, fp16 buffers.
// ---------------------------------------------------------------------------

#define D 64
#define MAXN 100352
#define MAXR 5
#define MAXE 1048576

__device__ __half g_bufA[(size_t)MAXR * MAXN * D];
__device__ __half g_bufB[(size_t)MAXR * MAXN * D];
__device__ float  g_sum [(size_t)MAXN * D];
__device__ int    g_deg  [MAXR * MAXN];
__device__ int    g_start[MAXR * MAXN + 1];
__device__ int    g_bsum [2048];
__device__ int2   g_edges[(size_t)MAXR * MAXE];
__device__ __half g_w1t[MAXR * 64 * 64];   // transposed [n][k] fp16
__device__ __half g_w2t[MAXR * 64 * 64];
__device__ float  g_c1 [MAXR * 64];
__device__ float  g_b2 [MAXR * 64];

__device__ __forceinline__ void red_add_v4(float* addr, float4 v) {
    asm volatile("red.global.add.v4.f32 [%0], {%1,%2,%3,%4};"
                 :: "l"(addr), "f"(v.x), "f"(v.y), "f"(v.z), "f"(v.w)
                 : "memory");
}

#define MMA16816(c0, c1, c2, c3, a0, a1, a2, a3, b0, b1) \
    asm volatile("mma.sync.aligned.m16n8k16.row.col.f32.f16.f16.f32 " \
                 "{%0,%1,%2,%3}, {%4,%5,%6,%7}, {%8,%9}, {%0,%1,%2,%3};" \
                 : "+f"(c0), "+f"(c1), "+f"(c2), "+f"(c3) \
                 : "r"(a0), "r"(a1), "r"(a2), "r"(a3), "r"(b0), "r"(b1))

// ---------------------------------------------------------------------------
// CSR build
// ---------------------------------------------------------------------------
__global__ void zero_deg_kernel(int* __restrict__ deg, int tot)
{
    int i = blockIdx.x * blockDim.x + threadIdx.x;
    if (i < tot) deg[i] = 0;
}

__global__ void hist_kernel(const int* __restrict__ rows, int E, int N,
                            int* __restrict__ deg, int tot)
{
    int i = blockIdx.x * blockDim.x + threadIdx.x;
    if (i >= tot) return;
    int r = i / E;
    atomicAdd(&deg[r * N + rows[i]], 1);
}

__global__ void __launch_bounds__(1024) scanA_kernel(
    const int* __restrict__ deg, int tot,
    int* __restrict__ out, int* __restrict__ bsum)
{
    __shared__ int sm[1024];
    int i = blockIdx.x * 1024 + threadIdx.x;
    int v = (i < tot) ? deg[i] : 0;
    sm[threadIdx.x] = v;
    __syncthreads();
    #pragma unroll
    for (int o = 1; o < 1024; o <<= 1) {
        int t = (threadIdx.x >= o) ? sm[threadIdx.x - o] : 0;
        __syncthreads();
        sm[threadIdx.x] += t;
        __syncthreads();
    }
    if (i < tot) out[i] = sm[threadIdx.x] - v;
    if (threadIdx.x == 1023) bsum[blockIdx.x] = sm[1023];
}

__global__ void __launch_bounds__(1024) scanB_kernel(int* __restrict__ bsum, int nblk)
{
    __shared__ int sm[2048];
    for (int i = threadIdx.x; i < 2048; i += 1024)
        sm[i] = (i < nblk) ? bsum[i] : 0;
    __syncthreads();
    for (int o = 1; o < 2048; o <<= 1) {
        int t0 = (threadIdx.x >= o) ? sm[threadIdx.x - o] : 0;
        int i1 = threadIdx.x + 1024;
        int t1 = (i1 >= o) ? sm[i1 - o] : 0;
        __syncthreads();
        sm[threadIdx.x] += t0;
        sm[i1] += t1;
        __syncthreads();
    }
    int v0 = (threadIdx.x < nblk) ? ((threadIdx.x == 0) ? 0 : sm[threadIdx.x - 1]) : 0;
    int i1 = threadIdx.x + 1024;
    int v1 = (i1 < nblk) ? sm[i1 - 1] : 0;
    __syncthreads();
    if (threadIdx.x < nblk) bsum[threadIdx.x] = v0;
    if (i1 < nblk) bsum[i1] = v1;
}

__global__ void __launch_bounds__(1024) scanC_kernel(
    int* __restrict__ start, int* __restrict__ cursor,
    const int* __restrict__ bsum, int tot, int totE)
{
    int i = blockIdx.x * 1024 + threadIdx.x;
    if (i < tot) {
        int v = start[i] + bsum[blockIdx.x];
        start[i]  = v;
        cursor[i] = v;
    }
    if (i == 0) start[tot] = totE;
}

__global__ void scatter_kernel(const int* __restrict__ rows,
                               const int* __restrict__ cols,
                               const float* __restrict__ vals,
                               int E, int N, int* __restrict__ cursor,
                               int2* __restrict__ edges, int tot)
{
    int i = blockIdx.x * blockDim.x + threadIdx.x;
    if (i >= tot) return;
    int r = i / E;
    int pos = atomicAdd(&cursor[r * N + rows[i]], 1);
    edges[pos] = make_int2(cols[i], __float_as_int(vals[i]));
}

__global__ void zero_sum_kernel(float4* __restrict__ sum, int n4)
{
    int i = blockIdx.x * blockDim.x + threadIdx.x;
    if (i < n4) sum[i] = make_float4(0.f, 0.f, 0.f, 0.f);
}

// ---------------------------------------------------------------------------
// Prep: per rating r, build fp16 transposed weights and fused bias c1.
//   W1t[n][k] = W1[r][k][n]  (k in 0..63, the "A-half" of W1)
//   c1[n]     = b1[r][n] + sum_k rating_emb[r][k] * W1[r][64+k][n]
//   W2t[n][k] = W2[r][k][n];  b2 copy.
// ---------------------------------------------------------------------------
__global__ void __launch_bounds__(256) prep_kernel(
    const float* __restrict__ W1, const float* __restrict__ b1,
    const float* __restrict__ W2, const float* __restrict__ b2,
    const float* __restrict__ rating_emb,
    __half* __restrict__ w1t, __half* __restrict__ w2t,
    float* __restrict__ c1g, float* __restrict__ b2g)
{
    const int r = blockIdx.x;
    const int tid = threadIdx.x;
    const float* W1r = W1 + (size_t)r * 128 * 64;
    const float* W2r = W2 + (size_t)r * 64 * 64;

    for (int i = tid; i < 4096; i += 256) {
        int k = i >> 6, n = i & 63;
        w1t[(size_t)r * 4096 + n * 64 + k] = __float2half(W1r[i]);
        w2t[(size_t)r * 4096 + n * 64 + k] = __float2half(W2r[i]);
    }
    if (tid < 64) {
        float c = b1[r * 64 + tid];
        #pragma unroll 8
        for (int k = 0; k < 64; k++)
            c += rating_emb[r * 64 + k] * W1r[(64 + k) * 64 + tid];
        c1g[r * 64 + tid] = c;
        b2g[r * 64 + tid] = b2[r * 64 + tid];
    }
}

// ---------------------------------------------------------------------------
// HMMA MLP (blockIdx.y = rating): 256 thr / 8 warps, 128 rows per block,
// 16 rows per warp. h = leaky(x @ W1a + c1) @ W2 + b2 -> fp16 out.
// ---------------------------------------------------------------------------
#define XS_STRIDE 72
#define WS_STRIDE 72

__global__ void __launch_bounds__(256) mlp_hmma_kernel(
    const float* __restrict__ user_emb, const float* __restrict__ item_emb,
    int U, int N,
    const __half* __restrict__ w1t, const __half* __restrict__ w2t,
    const float* __restrict__ c1g, const float* __restrict__ b2g,
    __half* __restrict__ outbuf)
{
    __shared__ __half xs [128 * XS_STRIDE];
    __shared__ __half w1s[64 * WS_STRIDE];
    __shared__ __half w2s[64 * WS_STRIDE];
    __shared__ float  c1s[64];
    __shared__ float  b2s[64];

    const int r = blockIdx.y;
    const int row0 = blockIdx.x * 128;
    const int tid = threadIdx.x;
    __half* prevbuf = outbuf + (size_t)r * MAXN * D;

    // weights -> smem (half2 units, padded stride)
    const __half* w1g = w1t + (size_t)r * 4096;
    const __half* w2g = w2t + (size_t)r * 4096;
    for (int i = tid; i < 2048; i += 256) {
        int n = i >> 5, kk = (i & 31) * 2;
        *(__half2*)&w1s[n * WS_STRIDE + kk] = *(const __half2*)&w1g[n * 64 + kk];
        *(__half2*)&w2s[n * WS_STRIDE + kk] = *(const __half2*)&w2g[n * 64 + kk];
    }
    if (tid < 64) {
        c1s[tid] = c1g[r * 64 + tid];
        b2s[tid] = b2g[r * 64 + tid];
    }
    // x -> smem fp16
    for (int i = tid; i < 128 * 16; i += 256) {
        int rr = i >> 4, c4 = i & 15;
        int row = row0 + rr;
        float4 v = make_float4(0.f, 0.f, 0.f, 0.f);
        if (row < N) {
            const float* src = (row < U) ? (user_emb + (size_t)row * 64)
                                         : (item_emb + (size_t)(row - U) * 64);
            v = ((const float4*)src)[c4];
        }
        *(__half2*)&xs[rr * XS_STRIDE + c4 * 4]     = __floats2half2_rn(v.x, v.y);
        *(__half2*)&xs[rr * XS_STRIDE + c4 * 4 + 2] = __floats2half2_rn(v.z, v.w);
    }
    __syncthreads();

    const int wid  = tid >> 5;
    const int lane = tid & 31;
    const int g    = lane >> 2;
    const int tig  = lane & 3;
    const int ar   = wid * 16;           // warp row base within tile

    unsigned a[4][4];

    // ---- layer 1: A frags from xs ----
    #pragma unroll
    for (int ks = 0; ks < 4; ks++) {
        int k0 = ks * 16;
        a[ks][0] = *(unsigned*)&xs[(ar + g)     * XS_STRIDE + k0 + tig * 2];
        a[ks][1] = *(unsigned*)&xs[(ar + g + 8) * XS_STRIDE + k0 + tig * 2];
        a[ks][2] = *(unsigned*)&xs[(ar + g)     * XS_STRIDE + k0 + tig * 2 + 8];
        a[ks][3] = *(unsigned*)&xs[(ar + g + 8) * XS_STRIDE + k0 + tig * 2 + 8];
    }

    #pragma unroll
    for (int nt = 0; nt < 8; nt++) {
        float c0 = 0.f, c1 = 0.f, c2 = 0.f, c3 = 0.f;
        #pragma unroll
        for (int ks = 0; ks < 4; ks++) {
            int k0 = ks * 16;
            unsigned b0 = *(unsigned*)&w1s[(nt * 8 + g) * WS_STRIDE + k0 + tig * 2];
            unsigned b1 = *(unsigned*)&w1s[(nt * 8 + g) * WS_STRIDE + k0 + tig * 2 + 8];
            MMA16816(c0, c1, c2, c3, a[ks][0], a[ks][1], a[ks][2], a[ks][3], b0, b1);
        }
        int col = nt * 8 + tig * 2;
        float bc0 = c1s[col], bc1 = c1s[col + 1];
        float v0 = c0 + bc0; v0 = (v0 > 0.f) ? v0 : 0.01f * v0;
        float v1 = c1 + bc1; v1 = (v1 > 0.f) ? v1 : 0.01f * v1;
        float v2 = c2 + bc0; v2 = (v2 > 0.f) ? v2 : 0.01f * v2;
        float v3 = c3 + bc1; v3 = (v3 > 0.f) ? v3 : 0.01f * v3;
        *(__half2*)&xs[(ar + g)     * XS_STRIDE + col] = __floats2half2_rn(v0, v1);
        *(__half2*)&xs[(ar + g + 8) * XS_STRIDE + col] = __floats2half2_rn(v2, v3);
    }
    __syncwarp();

    // ---- layer 2: A frags from h (in xs) ----
    #pragma unroll
    for (int ks = 0; ks < 4; ks++) {
        int k0 = ks * 16;
        a[ks][0] = *(unsigned*)&xs[(ar + g)     * XS_STRIDE + k0 + tig * 2];
        a[ks][1] = *(unsigned*)&xs[(ar + g + 8) * XS_STRIDE + k0 + tig * 2];
        a[ks][2] = *(unsigned*)&xs[(ar + g)     * XS_STRIDE + k0 + tig * 2 + 8];
        a[ks][3] = *(unsigned*)&xs[(ar + g + 8) * XS_STRIDE + k0 + tig * 2 + 8];
    }
    __syncwarp();

    #pragma unroll
    for (int nt = 0; nt < 8; nt++) {
        float c0 = 0.f, c1 = 0.f, c2 = 0.f, c3 = 0.f;
        #pragma unroll
        for (int ks = 0; ks < 4; ks++) {
            int k0 = ks * 16;
            unsigned b0 = *(unsigned*)&w2s[(nt * 8 + g) * WS_STRIDE + k0 + tig * 2];
            unsigned b1 = *(unsigned*)&w2s[(nt * 8 + g) * WS_STRIDE + k0 + tig * 2 + 8];
            MMA16816(c0, c1, c2, c3, a[ks][0], a[ks][1], a[ks][2], a[ks][3], b0, b1);
        }
        int col = nt * 8 + tig * 2;
        float bc0 = b2s[col], bc1 = b2s[col + 1];
        *(__half2*)&xs[(ar + g)     * XS_STRIDE + col] =
            __floats2half2_rn(c0 + bc0, c1 + bc1);
        *(__half2*)&xs[(ar + g + 8) * XS_STRIDE + col] =
            __floats2half2_rn(c2 + bc0, c3 + bc1);
    }
    __syncthreads();

    // coalesced store (rows beyond N are < MAXN, harmless)
    for (int i = tid; i < 128 * 16; i += 256) {
        int rr = i >> 4, c = i & 15;
        uint2 v = *(uint2*)&xs[rr * XS_STRIDE + c * 4];
        *(uint2*)(prevbuf + (size_t)(row0 + rr) * 64 + c * 4) = v;
    }
}

// ---------------------------------------------------------------------------
// CSR SpMM over ALL ratings (fp16 gather, fp32 accumulate).
// mode 0: next = acc; red.add(sum, h + acc)   (sum pre-zeroed)
// mode 1: next = acc
// mode 2: red.add(sum, p2 + (mask ? acc : p2))
// ---------------------------------------------------------------------------
__global__ void __launch_bounds__(256) spmm_all_kernel(
    const int* __restrict__ start, const int2* __restrict__ edges,
    const __half* __restrict__ prevbase, __half* __restrict__ nextbase,
    float* __restrict__ sum, int N, int RN,
    int mode, unsigned long long mask)
{
    int gr   = blockIdx.x * 32 + (threadIdx.x >> 3);
    int lane = threadIdx.x & 7;
    if (gr >= RN) return;
    int r   = gr / N;
    int row = gr - r * N;

    const __half* prev_r = prevbase + (size_t)r * MAXN * D;

    int s = __ldg(start + gr);
    int e = __ldg(start + gr + 1);

    float acc[8];
    #pragma unroll
    for (int d = 0; d < 8; d++) acc[d] = 0.f;

    int j = s;
    for (; j + 1 < e; j += 2) {
        int2 e0 = __ldg(edges + j);
        int2 e1 = __ldg(edges + j + 1);
        float4 r0 = __ldg((const float4*)(prev_r + (size_t)e0.x * 64) + lane);
        float4 r1 = __ldg((const float4*)(prev_r + (size_t)e1.x * 64) + lane);
        float v0 = __int_as_float(e0.y);
        float v1 = __int_as_float(e1.y);
        const __half2* h0 = (const __half2*)&r0;
        const __half2* h1 = (const __half2*)&r1;
        #pragma unroll
        for (int q = 0; q < 4; q++) {
            float2 f0 = __half22float2(h0[q]);
            float2 f1 = __half22float2(h1[q]);
            acc[2 * q]     += v0 * f0.x + v1 * f1.x;
            acc[2 * q + 1] += v0 * f0.y + v1 * f1.y;
        }
    }
    if (j < e) {
        int2 e0 = __ldg(edges + j);
        float4 r0 = __ldg((const float4*)(prev_r + (size_t)e0.x * 64) + lane);
        float v0 = __int_as_float(e0.y);
        const __half2* h0 = (const __half2*)&r0;
        #pragma unroll
        for (int q = 0; q < 4; q++) {
            float2 f0 = __half22float2(h0[q]);
            acc[2 * q]     += v0 * f0.x;
            acc[2 * q + 1] += v0 * f0.y;
        }
    }

    const size_t goff = (size_t)r * MAXN * D + (size_t)row * 64 + lane * 8;
    const size_t soff = (size_t)row * 64 + lane * 8;

    if (mode == 0) {
        __half2 o0 = __floats2half2_rn(acc[0], acc[1]);
        __half2 o1 = __floats2half2_rn(acc[2], acc[3]);
        __half2 o2 = __floats2half2_rn(acc[4], acc[5]);
        __half2 o3 = __floats2half2_rn(acc[6], acc[7]);
        uint4 st = make_uint4(*(unsigned*)&o0, *(unsigned*)&o1,
                              *(unsigned*)&o2, *(unsigned*)&o3);
        *(uint4*)(nextbase + goff) = st;
        float4 hraw = __ldg((const float4*)(prevbase + goff));
        const __half2* hh = (const __half2*)&hraw;
        float hv[8];
        #pragma unroll
        for (int q = 0; q < 4; q++) {
            float2 f = __half22float2(hh[q]);
            hv[2 * q] = f.x; hv[2 * q + 1] = f.y;
        }
        red_add_v4(sum + soff, make_float4(hv[0] + acc[0], hv[1] + acc[1],
                                           hv[2] + acc[2], hv[3] + acc[3]));
        red_add_v4(sum + soff + 4, make_float4(hv[4] + acc[4], hv[5] + acc[5],
                                               hv[6] + acc[6], hv[7] + acc[7]));
    } else if (mode == 1) {
        __half2 o0 = __floats2half2_rn(acc[0], acc[1]);
        __half2 o1 = __floats2half2_rn(acc[2], acc[3]);
        __half2 o2 = __floats2half2_rn(acc[4], acc[5]);
        __half2 o3 = __floats2half2_rn(acc[6], acc[7]);
        uint4 st = make_uint4(*(unsigned*)&o0, *(unsigned*)&o1,
                              *(unsigned*)&o2, *(unsigned*)&o3);
        *(uint4*)(nextbase + goff) = st;
    } else {
        float4 praw = __ldg((const float4*)(prevbase + goff));
        const __half2* ph = (const __half2*)&praw;
        float pv[8];
        #pragma unroll
        for (int q = 0; q < 4; q++) {
            float2 f = __half22float2(ph[q]);
            pv[2 * q] = f.x; pv[2 * q + 1] = f.y;
        }
        unsigned mb = (unsigned)((mask >> (lane * 8)) & 0xFFull);
        float contrib[8];
        #pragma unroll
        for (int d = 0; d < 8; d++)
            contrib[d] = pv[d] + (((mb >> d) & 1u) ? acc[d] : pv[d]);
        red_add_v4(sum + soff, make_float4(contrib[0], contrib[1],
                                           contrib[2], contrib[3]));
        red_add_v4(sum + soff + 4, make_float4(contrib[4], contrib[5],
                                               contrib[6], contrib[7]));
    }
}

// ---------------------------------------------------------------------------
// Final: out[b] = (sum[u] . sum[U+i]) / R^2
// ---------------------------------------------------------------------------
__global__ void final_kernel(const int* __restrict__ users,
                             const int* __restrict__ items,
                             const float* __restrict__ sum,
                             int U, float invR2,
                             float* __restrict__ out, int B)
{
    int b = blockIdx.x * (blockDim.x >> 5) + (threadIdx.x >> 5);
    int lane = threadIdx.x & 31;
    if (b >= B) return;
    int u = users[b];
    int it = items[b];
    const float* pu = sum + (size_t)u * 64;
    const float* pi = sum + ((size_t)U + it) * 64;
    float acc = pu[lane] * pi[lane] + pu[lane + 32] * pi[lane + 32];
    #pragma unroll
    for (int off = 16; off; off >>= 1)
        acc += __shfl_xor_sync(0xffffffffu, acc, off);
    if (lane == 0) out[b] = acc * invR2;
}

// ---------------------------------------------------------------------------
// Host: numpy MT19937 RandomState(2).permutation(64) -> layer-2 mask bits
// ---------------------------------------------------------------------------
static unsigned long long compute_layer2_mask(int d)
{
    const int NN = 624, MM = 397;
    unsigned int key[624];
    unsigned int s = 2u;
    for (int i = 0; i < NN; i++) {
        key[i] = s;
        s = 1812433253u * (s ^ (s >> 30)) + (unsigned)i + 1u;
    }
    int pos = NN;
    auto next_u32 = [&]() -> unsigned int {
        if (pos == NN) {
            for (int i = 0; i < NN; i++) {
                unsigned int y = (key[i] & 0x80000000u) |
                                 (key[(i + 1) % NN] & 0x7fffffffu);
                unsigned int v = key[(i + MM) % NN] ^ (y >> 1);
                if (y & 1u) v ^= 0x9908b0dfu;
                key[i] = v;
            }
            pos = 0;
        }
        unsigned int y = key[pos++];
        y ^= y >> 11;
        y ^= (y << 7)  & 0x9d2c5680u;
        y ^= (y << 15) & 0xefc60000u;
        y ^= y >> 18;
        return y;
    };
    int perm[64];
    for (int i = 0; i < d; i++) perm[i] = i;
    for (int i = d - 1; i > 0; i--) {
        unsigned int m = (unsigned)i;
        m |= m >> 1; m |= m >> 2; m |= m >> 4; m |= m >> 8; m |= m >> 16;
        unsigned int j;
        do { j = next_u32() & m; } while (j > (unsigned)i);
        int t = perm[i]; perm[i] = perm[j]; perm[j] = t;
    }
    double ratio = 1.0 - log(1.0 / 2.0 + 1.0);
    int nm = (int)(ratio * d);
    unsigned long long bits = 0ull;
    for (int i = 0; i < d; i++)
        if (perm[i] >= nm) bits |= (1ull << i);
    return bits;
}

// ---------------------------------------------------------------------------
extern "C" void kernel_launch(void* const* d_in, const int* in_sizes, int n_in,
                              void* d_out, int out_size)
{
    const int*   users      = (const int*)  d_in[0];
    const int*   items      = (const int*)  d_in[1];
    const float* user_emb   = (const float*)d_in[2];
    const float* item_emb   = (const float*)d_in[3];
    const float* rating_emb = (const float*)d_in[4];
    const float* W1         = (const float*)d_in[5];
    const float* b1         = (const float*)d_in[6];
    const float* W2         = (const float*)d_in[7];
    const float* b2         = (const float*)d_in[8];
    const int*   rows       = (const int*)  d_in[9];
    const int*   cols       = (const int*)  d_in[10];
    const float* vals       = (const float*)d_in[11];

    const int B = in_sizes[0];
    const int U = in_sizes[2] / D;
    const int I = in_sizes[3] / D;
    const int N = U + I;
    const int R = in_sizes[4] / D;
    const int E = in_sizes[9] / R;

    __half *bufA, *bufB, *w1t, *w2t;
    float *sumb, *c1g, *b2g;
    int *deg, *startp, *bsum;
    int2 *edges;
    cudaGetSymbolAddress((void**)&bufA,  g_bufA);
    cudaGetSymbolAddress((void**)&bufB,  g_bufB);
    cudaGetSymbolAddress((void**)&sumb,  g_sum);
    cudaGetSymbolAddress((void**)&deg,   g_deg);
    cudaGetSymbolAddress((void**)&startp,g_start);
    cudaGetSymbolAddress((void**)&bsum,  g_bsum);
    cudaGetSymbolAddress((void**)&edges, g_edges);
    cudaGetSymbolAddress((void**)&w1t,   g_w1t);
    cudaGetSymbolAddress((void**)&w2t,   g_w2t);
    cudaGetSymbolAddress((void**)&c1g,   g_c1);
    cudaGetSymbolAddress((void**)&b2g,   g_b2);

    const unsigned long long mask2 = compute_layer2_mask(D);

    // ---- CSR build (all ratings) ----
    const int totRN = R * N;
    const int totRE = R * E;
    const int nblk  = (totRN + 1023) / 1024;

    zero_deg_kernel<<<(totRN + 255) / 256, 256>>>(deg, totRN);
    hist_kernel<<<(totRE + 255) / 256, 256>>>(rows, E, N, deg, totRE);
    scanA_kernel<<<nblk, 1024>>>(deg, totRN, startp, bsum);
    scanB_kernel<<<1, 1024>>>(bsum, nblk);
    scanC_kernel<<<nblk, 1024>>>(startp, deg, bsum, totRN, totRE);
    scatter_kernel<<<(totRE + 255) / 256, 256>>>(rows, cols, vals, E, N,
                                                 deg, edges, totRE);

    // ---- zero sum + weight prep ----
    const int n4 = N * (D / 4);
    zero_sum_kernel<<<(n4 + 255) / 256, 256>>>((float4*)sumb, n4);
    prep_kernel<<<R, 256>>>(W1, b1, W2, b2, rating_emb, w1t, w2t, c1g, b2g);

    // ---- HMMA MLP for all ratings ----
    dim3 mlp_grid((N + 127) / 128, R);
    mlp_hmma_kernel<<<mlp_grid, 256>>>(user_emb, item_emb, U, N,
                                       w1t, w2t, c1g, b2g, bufA);

    // ---- 3 SpMM layers, each covering all ratings ----
    const int spmm_grid = (totRN + 31) / 32;
    spmm_all_kernel<<<spmm_grid, 256>>>(startp, edges, bufA, bufB, sumb,
                                        N, totRN, 0, 0ull);
    spmm_all_kernel<<<spmm_grid, 256>>>(startp, edges, bufB, bufA, sumb,
                                        N, totRN, 1, 0ull);
    spmm_all_kernel<<<spmm_grid, 256>>>(startp, edges, bufA, bufB, sumb,
                                        N, totRN, 2, mask2);

    const float invR2 = 1.0f / (float)(R * R);
    const int fin_grid = (B + 7) / 8;
    final_kernel<<<fin_grid, 256>>>(users, items, sumb, U, invR2,
                                    (float*)d_out, B);
}

// round 7
// speedup vs baseline: 2.8219x; 1.1770x over previous
#include <cuda_runtime.h>
#include <cuda_fp16.h>
#include <math.h>
#include <stdint.h>

// ---------------------------------------------------------------------------
// DCGCN: U=I=50000 (N=100000), R=5, D=64, E=1e6/rating, B=8192. Output f32[B].
// R7: R5 structure (no side streams!) + memset nodes + unroll-4 SpMM.
// ---------------------------------------------------------------------------

#define D 64
#define MAXN 100352
#define MAXR 5
#define MAXE 1048576

__device__ __half g_bufA[(size_t)MAXR * MAXN * D];
__device__ __half g_bufB[(size_t)MAXR * MAXN * D];
__device__ float  g_sum [(size_t)MAXN * D];
__device__ int    g_deg  [MAXR * MAXN];
__device__ int    g_start[MAXR * MAXN + 1];
__device__ int    g_bsum [2048];
__device__ int2   g_edges[(size_t)MAXR * MAXE];
__device__ __half g_w1t[MAXR * 64 * 64];
__device__ __half g_w2t[MAXR * 64 * 64];
__device__ float  g_c1 [MAXR * 64];
__device__ float  g_b2 [MAXR * 64];

__device__ __forceinline__ void red_add_v4(float* addr, float4 v) {
    asm volatile("red.global.add.v4.f32 [%0], {%1,%2,%3,%4};"
                 :: "l"(addr), "f"(v.x), "f"(v.y), "f"(v.z), "f"(v.w)
                 : "memory");
}

#define MMA16816(c0, c1, c2, c3, a0, a1, a2, a3, b0, b1) \
    asm volatile("mma.sync.aligned.m16n8k16.row.col.f32.f16.f16.f32 " \
                 "{%0,%1,%2,%3}, {%4,%5,%6,%7}, {%8,%9}, {%0,%1,%2,%3};" \
                 : "+f"(c0), "+f"(c1), "+f"(c2), "+f"(c3) \
                 : "r"(a0), "r"(a1), "r"(a2), "r"(a3), "r"(b0), "r"(b1))

// ---------------------------------------------------------------------------
// CSR build
// ---------------------------------------------------------------------------
__global__ void hist_kernel(const int* __restrict__ rows, int E, int N,
                            int* __restrict__ deg, int tot)
{
    int i = blockIdx.x * blockDim.x + threadIdx.x;
    if (i >= tot) return;
    int r = i / E;
    atomicAdd(&deg[r * N + rows[i]], 1);
}

__global__ void __launch_bounds__(1024) scanA_kernel(
    const int* __restrict__ deg, int tot,
    int* __restrict__ out, int* __restrict__ bsum)
{
    __shared__ int sm[1024];
    int i = blockIdx.x * 1024 + threadIdx.x;
    int v = (i < tot) ? deg[i] : 0;
    sm[threadIdx.x] = v;
    __syncthreads();
    #pragma unroll
    for (int o = 1; o < 1024; o <<= 1) {
        int t = (threadIdx.x >= o) ? sm[threadIdx.x - o] : 0;
        __syncthreads();
        sm[threadIdx.x] += t;
        __syncthreads();
    }
    if (i < tot) out[i] = sm[threadIdx.x] - v;
    if (threadIdx.x == 1023) bsum[blockIdx.x] = sm[1023];
}

__global__ void __launch_bounds__(1024) scanB_kernel(int* __restrict__ bsum, int nblk)
{
    __shared__ int sm[2048];
    for (int i = threadIdx.x; i < 2048; i += 1024)
        sm[i] = (i < nblk) ? bsum[i] : 0;
    __syncthreads();
    for (int o = 1; o < 2048; o <<= 1) {
        int t0 = (threadIdx.x >= o) ? sm[threadIdx.x - o] : 0;
        int i1 = threadIdx.x + 1024;
        int t1 = (i1 >= o) ? sm[i1 - o] : 0;
        __syncthreads();
        sm[threadIdx.x] += t0;
        sm[i1] += t1;
        __syncthreads();
    }
    int v0 = (threadIdx.x < nblk) ? ((threadIdx.x == 0) ? 0 : sm[threadIdx.x - 1]) : 0;
    int i1 = threadIdx.x + 1024;
    int v1 = (i1 < nblk) ? sm[i1 - 1] : 0;
    __syncthreads();
    if (threadIdx.x < nblk) bsum[threadIdx.x] = v0;
    if (i1 < nblk) bsum[i1] = v1;
}

__global__ void __launch_bounds__(1024) scanC_kernel(
    int* __restrict__ start, int* __restrict__ cursor,
    const int* __restrict__ bsum, int tot, int totE)
{
    int i = blockIdx.x * 1024 + threadIdx.x;
    if (i < tot) {
        int v = start[i] + bsum[blockIdx.x];
        start[i]  = v;
        cursor[i] = v;
    }
    if (i == 0) start[tot] = totE;
}

__global__ void scatter_kernel(const int* __restrict__ rows,
                               const int* __restrict__ cols,
                               const float* __restrict__ vals,
                               int E, int N, int* __restrict__ cursor,
                               int2* __restrict__ edges, int tot)
{
    int i = blockIdx.x * blockDim.x + threadIdx.x;
    if (i >= tot) return;
    int r = i / E;
    int pos = atomicAdd(&cursor[r * N + rows[i]], 1);
    edges[pos] = make_int2(cols[i], __float_as_int(vals[i]));
}

// ---------------------------------------------------------------------------
// Prep: per rating r, fp16 transposed weights + fused bias c1.
// ---------------------------------------------------------------------------
__global__ void __launch_bounds__(256) prep_kernel(
    const float* __restrict__ W1, const float* __restrict__ b1,
    const float* __restrict__ W2, const float* __restrict__ b2,
    const float* __restrict__ rating_emb,
    __half* __restrict__ w1t, __half* __restrict__ w2t,
    float* __restrict__ c1g, float* __restrict__ b2g)
{
    const int r = blockIdx.x;
    const int tid = threadIdx.x;
    const float* W1r = W1 + (size_t)r * 128 * 64;
    const float* W2r = W2 + (size_t)r * 64 * 64;

    for (int i = tid; i < 4096; i += 256) {
        int k = i >> 6, n = i & 63;
        w1t[(size_t)r * 4096 + n * 64 + k] = __float2half(W1r[i]);
        w2t[(size_t)r * 4096 + n * 64 + k] = __float2half(W2r[i]);
    }
    if (tid < 64) {
        float c = b1[r * 64 + tid];
        #pragma unroll 8
        for (int k = 0; k < 64; k++)
            c += rating_emb[r * 64 + k] * W1r[(64 + k) * 64 + tid];
        c1g[r * 64 + tid] = c;
        b2g[r * 64 + tid] = b2[r * 64 + tid];
    }
}

// ---------------------------------------------------------------------------
// HMMA MLP (blockIdx.y = rating): 256 thr / 8 warps, 128 rows per block.
// ---------------------------------------------------------------------------
#define XS_STRIDE 72
#define WS_STRIDE 72

__global__ void __launch_bounds__(256) mlp_hmma_kernel(
    const float* __restrict__ user_emb, const float* __restrict__ item_emb,
    int U, int N,
    const __half* __restrict__ w1t, const __half* __restrict__ w2t,
    const float* __restrict__ c1g, const float* __restrict__ b2g,
    __half* __restrict__ outbuf)
{
    __shared__ __half xs [128 * XS_STRIDE];
    __shared__ __half w1s[64 * WS_STRIDE];
    __shared__ __half w2s[64 * WS_STRIDE];
    __shared__ float  c1s[64];
    __shared__ float  b2s[64];

    const int r = blockIdx.y;
    const int row0 = blockIdx.x * 128;
    const int tid = threadIdx.x;
    __half* prevbuf = outbuf + (size_t)r * MAXN * D;

    const __half* w1g = w1t + (size_t)r * 4096;
    const __half* w2g = w2t + (size_t)r * 4096;
    for (int i = tid; i < 2048; i += 256) {
        int n = i >> 5, kk = (i & 31) * 2;
        *(__half2*)&w1s[n * WS_STRIDE + kk] = *(const __half2*)&w1g[n * 64 + kk];
        *(__half2*)&w2s[n * WS_STRIDE + kk] = *(const __half2*)&w2g[n * 64 + kk];
    }
    if (tid < 64) {
        c1s[tid] = c1g[r * 64 + tid];
        b2s[tid] = b2g[r * 64 + tid];
    }
    for (int i = tid; i < 128 * 16; i += 256) {
        int rr = i >> 4, c4 = i & 15;
        int row = row0 + rr;
        float4 v = make_float4(0.f, 0.f, 0.f, 0.f);
        if (row < N) {
            const float* src = (row < U) ? (user_emb + (size_t)row * 64)
                                         : (item_emb + (size_t)(row - U) * 64);
            v = ((const float4*)src)[c4];
        }
        *(__half2*)&xs[rr * XS_STRIDE + c4 * 4]     = __floats2half2_rn(v.x, v.y);
        *(__half2*)&xs[rr * XS_STRIDE + c4 * 4 + 2] = __floats2half2_rn(v.z, v.w);
    }
    __syncthreads();

    const int wid  = tid >> 5;
    const int lane = tid & 31;
    const int g    = lane >> 2;
    const int tig  = lane & 3;
    const int ar   = wid * 16;

    unsigned a[4][4];

    #pragma unroll
    for (int ks = 0; ks < 4; ks++) {
        int k0 = ks * 16;
        a[ks][0] = *(unsigned*)&xs[(ar + g)     * XS_STRIDE + k0 + tig * 2];
        a[ks][1] = *(unsigned*)&xs[(ar + g + 8) * XS_STRIDE + k0 + tig * 2];
        a[ks][2] = *(unsigned*)&xs[(ar + g)     * XS_STRIDE + k0 + tig * 2 + 8];
        a[ks][3] = *(unsigned*)&xs[(ar + g + 8) * XS_STRIDE + k0 + tig * 2 + 8];
    }

    #pragma unroll
    for (int nt = 0; nt < 8; nt++) {
        float c0 = 0.f, c1 = 0.f, c2 = 0.f, c3 = 0.f;
        #pragma unroll
        for (int ks = 0; ks < 4; ks++) {
            int k0 = ks * 16;
            unsigned b0 = *(unsigned*)&w1s[(nt * 8 + g) * WS_STRIDE + k0 + tig * 2];
            unsigned b1 = *(unsigned*)&w1s[(nt * 8 + g) * WS_STRIDE + k0 + tig * 2 + 8];
            MMA16816(c0, c1, c2, c3, a[ks][0], a[ks][1], a[ks][2], a[ks][3], b0, b1);
        }
        int col = nt * 8 + tig * 2;
        float bc0 = c1s[col], bc1 = c1s[col + 1];
        float v0 = c0 + bc0; v0 = (v0 > 0.f) ? v0 : 0.01f * v0;
        float v1 = c1 + bc1; v1 = (v1 > 0.f) ? v1 : 0.01f * v1;
        float v2 = c2 + bc0; v2 = (v2 > 0.f) ? v2 : 0.01f * v2;
        float v3 = c3 + bc1; v3 = (v3 > 0.f) ? v3 : 0.01f * v3;
        *(__half2*)&xs[(ar + g)     * XS_STRIDE + col] = __floats2half2_rn(v0, v1);
        *(__half2*)&xs[(ar + g + 8) * XS_STRIDE + col] = __floats2half2_rn(v2, v3);
    }
    __syncwarp();

    #pragma unroll
    for (int ks = 0; ks < 4; ks++) {
        int k0 = ks * 16;
        a[ks][0] = *(unsigned*)&xs[(ar + g)     * XS_STRIDE + k0 + tig * 2];
        a[ks][1] = *(unsigned*)&xs[(ar + g + 8) * XS_STRIDE + k0 + tig * 2];
        a[ks][2] = *(unsigned*)&xs[(ar + g)     * XS_STRIDE + k0 + tig * 2 + 8];
        a[ks][3] = *(unsigned*)&xs[(ar + g + 8) * XS_STRIDE + k0 + tig * 2 + 8];
    }
    __syncwarp();

    #pragma unroll
    for (int nt = 0; nt < 8; nt++) {
        float c0 = 0.f, c1 = 0.f, c2 = 0.f, c3 = 0.f;
        #pragma unroll
        for (int ks = 0; ks < 4; ks++) {
            int k0 = ks * 16;
            unsigned b0 = *(unsigned*)&w2s[(nt * 8 + g) * WS_STRIDE + k0 + tig * 2];
            unsigned b1 = *(unsigned*)&w2s[(nt * 8 + g) * WS_STRIDE + k0 + tig * 2 + 8];
            MMA16816(c0, c1, c2, c3, a[ks][0], a[ks][1], a[ks][2], a[ks][3], b0, b1);
        }
        int col = nt * 8 + tig * 2;
        float bc0 = b2s[col], bc1 = b2s[col + 1];
        *(__half2*)&xs[(ar + g)     * XS_STRIDE + col] =
            __floats2half2_rn(c0 + bc0, c1 + bc1);
        *(__half2*)&xs[(ar + g + 8) * XS_STRIDE + col] =
            __floats2half2_rn(c2 + bc0, c3 + bc1);
    }
    __syncthreads();

    for (int i = tid; i < 128 * 16; i += 256) {
        int rr = i >> 4, c = i & 15;
        uint2 v = *(uint2*)&xs[rr * XS_STRIDE + c * 4];
        *(uint2*)(prevbuf + (size_t)(row0 + rr) * 64 + c * 4) = v;
    }
}

// ---------------------------------------------------------------------------
// CSR SpMM over ALL ratings (fp16 gather, fp32 accumulate), unroll-4.
// mode 0: next = acc; red.add(sum, h + acc)   (sum pre-zeroed)
// mode 1: next = acc
// mode 2: red.add(sum, p2 + (mask ? acc : p2))
// ---------------------------------------------------------------------------
__device__ __forceinline__ void acc_edge(float* acc, float v, float4 raw)
{
    const __half2* h = (const __half2*)&raw;
    #pragma unroll
    for (int q = 0; q < 4; q++) {
        float2 f = __half22float2(h[q]);
        acc[2 * q]     += v * f.x;
        acc[2 * q + 1] += v * f.y;
    }
}

__global__ void __launch_bounds__(256) spmm_all_kernel(
    const int* __restrict__ start, const int2* __restrict__ edges,
    const __half* __restrict__ prevbase, __half* __restrict__ nextbase,
    float* __restrict__ sum, int N, int RN,
    int mode, unsigned long long mask)
{
    int gr   = blockIdx.x * 32 + (threadIdx.x >> 3);
    int lane = threadIdx.x & 7;
    if (gr >= RN) return;
    int r   = gr / N;
    int row = gr - r * N;

    const __half* prev_r = prevbase + (size_t)r * MAXN * D;

    int s = __ldg(start + gr);
    int e = __ldg(start + gr + 1);

    float acc[8];
    #pragma unroll
    for (int d = 0; d < 8; d++) acc[d] = 0.f;

    int j = s;
    for (; j + 3 < e; j += 4) {
        int2 e0 = __ldg(edges + j);
        int2 e1 = __ldg(edges + j + 1);
        int2 e2 = __ldg(edges + j + 2);
        int2 e3 = __ldg(edges + j + 3);
        float4 r0 = __ldg((const float4*)(prev_r + (size_t)e0.x * 64) + lane);
        float4 r1 = __ldg((const float4*)(prev_r + (size_t)e1.x * 64) + lane);
        float4 r2 = __ldg((const float4*)(prev_r + (size_t)e2.x * 64) + lane);
        float4 r3 = __ldg((const float4*)(prev_r + (size_t)e3.x * 64) + lane);
        acc_edge(acc, __int_as_float(e0.y), r0);
        acc_edge(acc, __int_as_float(e1.y), r1);
        acc_edge(acc, __int_as_float(e2.y), r2);
        acc_edge(acc, __int_as_float(e3.y), r3);
    }
    for (; j < e; j++) {
        int2 e0 = __ldg(edges + j);
        float4 r0 = __ldg((const float4*)(prev_r + (size_t)e0.x * 64) + lane);
        acc_edge(acc, __int_as_float(e0.y), r0);
    }

    const size_t goff = (size_t)r * MAXN * D + (size_t)row * 64 + lane * 8;
    const size_t soff = (size_t)row * 64 + lane * 8;

    if (mode == 0) {
        __half2 o0 = __floats2half2_rn(acc[0], acc[1]);
        __half2 o1 = __floats2half2_rn(acc[2], acc[3]);
        __half2 o2 = __floats2half2_rn(acc[4], acc[5]);
        __half2 o3 = __floats2half2_rn(acc[6], acc[7]);
        uint4 st = make_uint4(*(unsigned*)&o0, *(unsigned*)&o1,
                              *(unsigned*)&o2, *(unsigned*)&o3);
        *(uint4*)(nextbase + goff) = st;
        float4 hraw = __ldg((const float4*)(prevbase + goff));
        const __half2* hh = (const __half2*)&hraw;
        float hv[8];
        #pragma unroll
        for (int q = 0; q < 4; q++) {
            float2 f = __half22float2(hh[q]);
            hv[2 * q] = f.x; hv[2 * q + 1] = f.y;
        }
        red_add_v4(sum + soff, make_float4(hv[0] + acc[0], hv[1] + acc[1],
                                           hv[2] + acc[2], hv[3] + acc[3]));
        red_add_v4(sum + soff + 4, make_float4(hv[4] + acc[4], hv[5] + acc[5],
                                               hv[6] + acc[6], hv[7] + acc[7]));
    } else if (mode == 1) {
        __half2 o0 = __floats2half2_rn(acc[0], acc[1]);
        __half2 o1 = __floats2half2_rn(acc[2], acc[3]);
        __half2 o2 = __floats2half2_rn(acc[4], acc[5]);
        __half2 o3 = __floats2half2_rn(acc[6], acc[7]);
        uint4 st = make_uint4(*(unsigned*)&o0, *(unsigned*)&o1,
                              *(unsigned*)&o2, *(unsigned*)&o3);
        *(uint4*)(nextbase + goff) = st;
    } else {
        float4 praw = __ldg((const float4*)(prevbase + goff));
        const __half2* ph = (const __half2*)&praw;
        float pv[8];
        #pragma unroll
        for (int q = 0; q < 4; q++) {
            float2 f = __half22float2(ph[q]);
            pv[2 * q] = f.x; pv[2 * q + 1] = f.y;
        }
        unsigned mb = (unsigned)((mask >> (lane * 8)) & 0xFFull);
        float contrib[8];
        #pragma unroll
        for (int d = 0; d < 8; d++)
            contrib[d] = pv[d] + (((mb >> d) & 1u) ? acc[d] : pv[d]);
        red_add_v4(sum + soff, make_float4(contrib[0], contrib[1],
                                           contrib[2], contrib[3]));
        red_add_v4(sum + soff + 4, make_float4(contrib[4], contrib[5],
                                               contrib[6], contrib[7]));
    }
}

// ---------------------------------------------------------------------------
// Final: out[b] = (sum[u] . sum[U+i]) / R^2
// ---------------------------------------------------------------------------
__global__ void final_kernel(const int* __restrict__ users,
                             const int* __restrict__ items,
                             const float* __restrict__ sum,
                             int U, float invR2,
                             float* __restrict__ out, int B)
{
    int b = blockIdx.x * (blockDim.x >> 5) + (threadIdx.x >> 5);
    int lane = threadIdx.x & 31;
    if (b >= B) return;
    int u = users[b];
    int it = items[b];
    const float* pu = sum + (size_t)u * 64;
    const float* pi = sum + ((size_t)U + it) * 64;
    float acc = pu[lane] * pi[lane] + pu[lane + 32] * pi[lane + 32];
    #pragma unroll
    for (int off = 16; off; off >>= 1)
        acc += __shfl_xor_sync(0xffffffffu, acc, off);
    if (lane == 0) out[b] = acc * invR2;
}

// ---------------------------------------------------------------------------
// Host: numpy MT19937 RandomState(2).permutation(64) -> layer-2 mask bits
// ---------------------------------------------------------------------------
static unsigned long long compute_layer2_mask(int d)
{
    const int NN = 624, MM = 397;
    unsigned int key[624];
    unsigned int s = 2u;
    for (int i = 0; i < NN; i++) {
        key[i] = s;
        s = 1812433253u * (s ^ (s >> 30)) + (unsigned)i + 1u;
    }
    int pos = NN;
    auto next_u32 = [&]() -> unsigned int {
        if (pos == NN) {
            for (int i = 0; i < NN; i++) {
                unsigned int y = (key[i] & 0x80000000u) |
                                 (key[(i + 1) % NN] & 0x7fffffffu);
                unsigned int v = key[(i + MM) % NN] ^ (y >> 1);
                if (y & 1u) v ^= 0x9908b0dfu;
                key[i] = v;
            }
            pos = 0;
        }
        unsigned int y = key[pos++];
        y ^= y >> 11;
        y ^= (y << 7)  & 0x9d2c5680u;
        y ^= (y << 15) & 0xefc60000u;
        y ^= y >> 18;
        return y;
    };
    int perm[64];
    for (int i = 0; i < d; i++) perm[i] = i;
    for (int i = d - 1; i > 0; i--) {
        unsigned int m = (unsigned)i;
        m |= m >> 1; m |= m >> 2; m |= m >> 4; m |= m >> 8; m |= m >> 16;
        unsigned int j;
        do { j = next_u32() & m; } while (j > (unsigned)i);
        int t = perm[i]; perm[i] = perm[j]; perm[j] = t;
    }
    double ratio = 1.0 - log(1.0 / 2.0 + 1.0);
    int nm = (int)(ratio * d);
    unsigned long long bits = 0ull;
    for (int i = 0; i < d; i++)
        if (perm[i] >= nm) bits |= (1ull << i);
    return bits;
}

// ---------------------------------------------------------------------------
extern "C" void kernel_launch(void* const* d_in, const int* in_sizes, int n_in,
                              void* d_out, int out_size)
{
    const int*   users      = (const int*)  d_in[0];
    const int*   items      = (const int*)  d_in[1];
    const float* user_emb   = (const float*)d_in[2];
    const float* item_emb   = (const float*)d_in[3];
    const float* rating_emb = (const float*)d_in[4];
    const float* W1         = (const float*)d_in[5];
    const float* b1         = (const float*)d_in[6];
    const float* W2         = (const float*)d_in[7];
    const float* b2         = (const float*)d_in[8];
    const int*   rows       = (const int*)  d_in[9];
    const int*   cols       = (const int*)  d_in[10];
    const float* vals       = (const float*)d_in[11];

    const int B = in_sizes[0];
    const int U = in_sizes[2] / D;
    const int I = in_sizes[3] / D;
    const int N = U + I;
    const int R = in_sizes[4] / D;
    const int E = in_sizes[9] / R;

    __half *bufA, *bufB, *w1t, *w2t;
    float *sumb, *c1g, *b2g;
    int *deg, *startp, *bsum;
    int2 *edges;
    cudaGetSymbolAddress((void**)&bufA,  g_bufA);
    cudaGetSymbolAddress((void**)&bufB,  g_bufB);
    cudaGetSymbolAddress((void**)&sumb,  g_sum);
    cudaGetSymbolAddress((void**)&deg,   g_deg);
    cudaGetSymbolAddress((void**)&startp,g_start);
    cudaGetSymbolAddress((void**)&bsum,  g_bsum);
    cudaGetSymbolAddress((void**)&edges, g_edges);
    cudaGetSymbolAddress((void**)&w1t,   g_w1t);
    cudaGetSymbolAddress((void**)&w2t,   g_w2t);
    cudaGetSymbolAddress((void**)&c1g,   g_c1);
    cudaGetSymbolAddress((void**)&b2g,   g_b2);

    const unsigned long long mask2 = compute_layer2_mask(D);

    const int totRN = R * N;
    const int totRE = R * E;
    const int nblk  = (totRN + 1023) / 1024;

    // ---- CSR build (default stream; memset node instead of zero kernel) ----
    cudaMemsetAsync(deg, 0, totRN * sizeof(int), 0);
    hist_kernel<<<(totRE + 255) / 256, 256>>>(rows, E, N, deg, totRE);
    scanA_kernel<<<nblk, 1024>>>(deg, totRN, startp, bsum);
    scanB_kernel<<<1, 1024>>>(bsum, nblk);
    scanC_kernel<<<nblk, 1024>>>(startp, deg, bsum, totRN, totRE);
    scatter_kernel<<<(totRE + 255) / 256, 256>>>(rows, cols, vals, E, N,
                                                 deg, edges, totRE);

    // ---- sum zero + weight prep + HMMA MLP ----
    cudaMemsetAsync(sumb, 0, (size_t)N * D * sizeof(float), 0);
    prep_kernel<<<R, 256>>>(W1, b1, W2, b2, rating_emb, w1t, w2t, c1g, b2g);
    dim3 mlp_grid((N + 127) / 128, R);
    mlp_hmma_kernel<<<mlp_grid, 256>>>(user_emb, item_emb, U, N,
                                       w1t, w2t, c1g, b2g, bufA);

    // ---- 3 SpMM layers over all ratings ----
    const int spmm_grid = (totRN + 31) / 32;
    spmm_all_kernel<<<spmm_grid, 256>>>(startp, edges, bufA, bufB, sumb,
                                        N, totRN, 0, 0ull);
    spmm_all_kernel<<<spmm_grid, 256>>>(startp, edges, bufB, bufA, sumb,
                                        N, totRN, 1, 0ull);
    spmm_all_kernel<<<spmm_grid, 256>>>(startp, edges, bufA, bufB, sumb,
                                        N, totRN, 2, mask2);

    const float invR2 = 1.0f / (float)(R * R);
    const int fin_grid = (B + 7) / 8;
    final_kernel<<<fin_grid, 256>>>(users, items, sumb, U, invR2,
                                    (float*)d_out, B);
}